// round 11
// baseline (speedup 1.0000x reference)
#include <cuda_runtime.h>
#include <cuda_bf16.h>
#include <cstdint>

#define NODES 40000
#define EDGES 640000
#define DIM 128
#define GRAPHS 512
#define NEG_SLOPE 0.2f
#define BN_EPS 1e-5f

typedef unsigned long long u64;

// ---------------- scratch (no allocations allowed) ----------------
__device__ float d_h0[NODES * DIM];
__device__ float d_xl[NODES * DIM];
__device__ float d_xr[NODES * DIM];
__device__ __nv_bfloat16 d_hhi[NODES * DIM];
__device__ __nv_bfloat16 d_hlo[NODES * DIM];
__device__ __nv_bfloat16 d_whi[3 * 2 * DIM * DIM];
__device__ __nv_bfloat16 d_wlo[3 * 2 * DIM * DIM];
__device__ int d_deg[NODES];
__device__ int d_rowptr[NODES + 1];
__device__ int d_cursor[NODES];
__device__ int d_srcs[EDGES];

__device__ __forceinline__ uint32_t smem_u32(const void* p) {
    uint32_t a;
    asm("{ .reg .u64 t; cvta.to.shared.u64 t, %1; cvt.u32.u64 %0, t; }" : "=r"(a) : "l"(p));
    return a;
}
__device__ __forceinline__ void ldsm_x4(uint32_t* r, uint32_t addr) {
    asm volatile("ldmatrix.sync.aligned.m8n8.x4.shared.b16 {%0,%1,%2,%3}, [%4];"
                 : "=r"(r[0]), "=r"(r[1]), "=r"(r[2]), "=r"(r[3]) : "r"(addr));
}
__device__ __forceinline__ void ldsm_x4_t(uint32_t* r, uint32_t addr) {
    asm volatile("ldmatrix.sync.aligned.m8n8.x4.trans.shared.b16 {%0,%1,%2,%3}, [%4];"
                 : "=r"(r[0]), "=r"(r[1]), "=r"(r[2]), "=r"(r[3]) : "r"(addr));
}
__device__ __forceinline__ void mma16816(float* c, const uint32_t* a, const uint32_t* b) {
    asm volatile(
        "mma.sync.aligned.m16n8k16.row.col.f32.bf16.bf16.f32 "
        "{%0,%1,%2,%3}, {%4,%5,%6,%7}, {%8,%9}, {%0,%1,%2,%3};"
        : "+f"(c[0]), "+f"(c[1]), "+f"(c[2]), "+f"(c[3])
        : "r"(a[0]), "r"(a[1]), "r"(a[2]), "r"(a[3]), "r"(b[0]), "r"(b[1]));
}
__device__ __forceinline__ void cp16(uint32_t saddr, const void* gaddr) {
    asm volatile("cp.async.cg.shared.global [%0], [%1], 16;" :: "r"(saddr), "l"(gaddr));
}
#define CP_COMMIT() asm volatile("cp.async.commit_group;" ::: "memory")
#define CP_WAIT0()  asm volatile("cp.async.wait_group 0;" ::: "memory")

// ---------------- packed f32x2 helpers (sm_100+ base PTX) ----------------
__device__ __forceinline__ u64 pk2(float lo, float hi) {
    u64 r;
    asm("mov.b64 %0, {%1, %2};" : "=l"(r) : "f"(lo), "f"(hi));
    return r;
}
__device__ __forceinline__ void upk2(u64 v, float& lo, float& hi) {
    asm("mov.b64 {%0, %1}, %2;" : "=f"(lo), "=f"(hi) : "l"(v));
}
#define ADD2(o, a, b)    asm("add.rn.f32x2 %0, %1, %2;" : "=l"(o) : "l"(a), "l"(b))
#define MUL2(o, a, b)    asm("mul.rn.f32x2 %0, %1, %2;" : "=l"(o) : "l"(a), "l"(b))
#define FMA2(o, a, b, c) asm("fma.rn.f32x2 %0, %1, %2, %3;" : "=l"(o) : "l"(a), "l"(b), "l"(c))
#define ABS2(o, a)       asm("and.b64 %0, %1, 0x7FFFFFFF7FFFFFFF;" : "=l"(o) : "l"(a))

// packed leaky-dot: sum_c att_c * leaky(v_c + x_c), leaky(z) = 0.6z + 0.4|z|
__device__ __forceinline__ float pdot(u64 va, u64 vb, u64 X0, u64 X1,
                                      u64 w06a, u64 w06b, u64 w04a, u64 w04b) {
    u64 za, zb, aa, ab, u;
    ADD2(za, va, X0);
    ADD2(zb, vb, X1);
    ABS2(aa, za);
    ABS2(ab, zb);
    MUL2(u, zb, w06b);
    FMA2(u, ab, w04b, u);
    FMA2(u, za, w06a, u);
    FMA2(u, aa, w04a, u);
    float lo, hi;
    upk2(u, lo, hi);
    return lo + hi;
}
__device__ __forceinline__ float hred8(float d) {
    d += __shfl_xor_sync(0xffffffffu, d, 1);
    d += __shfl_xor_sync(0xffffffffu, d, 2);
    d += __shfl_xor_sync(0xffffffffu, d, 4);
    return d;
}

// ---------------- fused: convert x to bf16 hi/lo + zero deg ----------------
__global__ void k_convx_zero(const float* __restrict__ x) {
    int i = blockIdx.x * blockDim.x + threadIdx.x;
    if (i < NODES * DIM) {
        float v = x[i];
        __nv_bfloat16 h = __float2bfloat16(v);
        d_hhi[i] = h;
        d_hlo[i] = __float2bfloat16(v - __bfloat162float(h));
    }
    if (i < NODES) d_deg[i] = 0;
}

// ---------------- fused: degree histogram + convert weights ----------------
#define HIST_BLOCKS (EDGES / 256)
__global__ void k_hist_cw(const int* __restrict__ ei,
                          const float* __restrict__ Wl, const float* __restrict__ Wr) {
    if (blockIdx.x < HIST_BLOCKS) {
        int e = blockIdx.x * blockDim.x + threadIdx.x;
        atomicAdd(&d_deg[ei[EDGES + e]], 1);
    } else {
        int b = blockIdx.x - HIST_BLOCKS;
        int l = b >> 1, m = b & 1;
        const float* W = (m ? Wr : Wl) + (size_t)l * DIM * DIM;
        __nv_bfloat16* oh = d_whi + (size_t)(l * 2 + m) * DIM * DIM;
        __nv_bfloat16* ol = d_wlo + (size_t)(l * 2 + m) * DIM * DIM;
        for (int t = threadIdx.x; t < DIM * DIM; t += blockDim.x) {
            float v = W[t];
            __nv_bfloat16 h = __float2bfloat16(v);
            oh[t] = h;
            ol[t] = __float2bfloat16(v - __bfloat162float(h));
        }
    }
}

#define SCAN_CH 40
__global__ void k_scan() {
    __shared__ int ws[32];
    int t = threadIdx.x, lane = t & 31, wid = t >> 5;
    int base = t * SCAN_CH;
    int s = 0;
    #pragma unroll 4
    for (int k = 0; k < SCAN_CH; k++) {
        int idx = base + k;
        if (idx < NODES) s += d_deg[idx];
    }
    int x = s;
    #pragma unroll
    for (int o = 1; o < 32; o <<= 1) {
        int y = __shfl_up_sync(0xffffffffu, x, o);
        if (lane >= o) x += y;
    }
    if (lane == 31) ws[wid] = x;
    __syncthreads();
    if (wid == 0) {
        int sv = ws[lane], sx = sv;
        #pragma unroll
        for (int o = 1; o < 32; o <<= 1) {
            int y = __shfl_up_sync(0xffffffffu, sx, o);
            if (lane >= o) sx += y;
        }
        ws[lane] = sx - sv;
    }
    __syncthreads();
    int run = ws[wid] + x - s;
    #pragma unroll 4
    for (int k = 0; k < SCAN_CH; k++) {
        int idx = base + k;
        if (idx < NODES) {
            int dg = d_deg[idx];
            d_rowptr[idx] = run;
            d_cursor[idx] = run;
            run += dg;
        }
    }
    if (t == 1023) d_rowptr[NODES] = run;
}
__global__ void k_scatter(const int* __restrict__ ei) {
    int e = blockIdx.x * blockDim.x + threadIdx.x;
    if (e < EDGES) {
        int dst = ei[EDGES + e];
        int pos = atomicAdd(&d_cursor[dst], 1);
        d_srcs[pos] = ei[e];
    }
}

// ---------------- PROBE: new packed inner loop, 2500 nodes x 16 synthetic edges ----------------
#define PROBE_NODES 2500
__global__ __launch_bounds__(256) void k_gat_probe(const float* __restrict__ x,
                                                   const float* __restrict__ att)
{
    int i = blockIdx.x * 8 + (threadIdx.x >> 5);
    if (i >= PROBE_NODES) return;
    int lane = threadIdx.x & 31;
    int c = lane * 4;
    const char* xb = (const char*)x + (size_t)c * 4;

    float4 w = *(const float4*)(att + c);
    u64 w06a = pk2(0.6f * w.x, 0.6f * w.y), w06b = pk2(0.6f * w.z, 0.6f * w.w);
    u64 w04a = pk2(0.4f * w.x, 0.4f * w.y), w04b = pk2(0.4f * w.z, 0.4f * w.w);
    float4 xr4 = *(const float4*)(xb + ((uint32_t)i << 9));
    u64 X0 = pk2(xr4.x, xr4.y), X1 = pk2(xr4.z, xr4.w);
    u64 sva = X0, svb = X1;
    float m0 = hred8(pdot(sva, svb, X0, X1, w06a, w06b, w04a, w04b));
    float denom = 1.0f;
    u64 acc0 = sva, acc1 = svb;

    unsigned state = i * 2654435761u + 12345u;
    #pragma unroll 4
    for (int j = 0; j < 16; j += 4) {
        unsigned s0 = (state = state * 1664525u + 1013904223u) % NODES;
        unsigned s1 = (state = state * 1664525u + 1013904223u) % NODES;
        unsigned s2 = (state = state * 1664525u + 1013904223u) % NODES;
        unsigned s3 = (state = state * 1664525u + 1013904223u) % NODES;
        float4 v0 = *(const float4*)(xb + (s0 << 9));
        float4 v1 = *(const float4*)(xb + (s1 << 9));
        float4 v2 = *(const float4*)(xb + (s2 << 9));
        float4 v3 = *(const float4*)(xb + (s3 << 9));
        u64 v0a = pk2(v0.x, v0.y), v0b = pk2(v0.z, v0.w);
        u64 v1a = pk2(v1.x, v1.y), v1b = pk2(v1.z, v1.w);
        u64 v2a = pk2(v2.x, v2.y), v2b = pk2(v2.z, v2.w);
        u64 v3a = pk2(v3.x, v3.y), v3b = pk2(v3.z, v3.w);
        float a0 = __expf(hred8(pdot(v0a, v0b, X0, X1, w06a, w06b, w04a, w04b)) - m0);
        float a1 = __expf(hred8(pdot(v1a, v1b, X0, X1, w06a, w06b, w04a, w04b)) - m0);
        float a2 = __expf(hred8(pdot(v2a, v2b, X0, X1, w06a, w06b, w04a, w04b)) - m0);
        float a3 = __expf(hred8(pdot(v3a, v3b, X0, X1, w06a, w06b, w04a, w04b)) - m0);
        denom += (a0 + a1) + (a2 + a3);
        u64 A0 = pk2(a0, a0), A1 = pk2(a1, a1), A2 = pk2(a2, a2), A3 = pk2(a3, a3);
        FMA2(acc0, v0a, A0, acc0); FMA2(acc1, v0b, A0, acc1);
        FMA2(acc0, v1a, A1, acc0); FMA2(acc1, v1b, A1, acc1);
        FMA2(acc0, v2a, A2, acc0); FMA2(acc1, v2b, A2, acc1);
        FMA2(acc0, v3a, A3, acc0); FMA2(acc1, v3b, A3, acc1);
    }
    float inv = 1.0f / denom;
    float ax, ay, az, aw;
    upk2(acc0, ax, ay);
    upk2(acc1, az, aw);
    float4 o = {ax * inv, ay * inv, az * inv, aw * inv};
    *(float4*)(d_xl + (size_t)i * DIM + c) = o;   // dead store (gemm overwrites)
}

// ---------------- persistent HMMA dual GEMM (R8 split version) ----------------
#define SW_HI 0
#define SW_LO 32768
#define SA_BUF 65536
#define ABUF_SZ 32768
#define GSMEM 131072
#define NTILES (NODES / 64)

__global__ __launch_bounds__(256, 1) void k_gemm_tc(
    const __nv_bfloat16* __restrict__ Ahi, const __nv_bfloat16* __restrict__ Alo,
    const __nv_bfloat16* __restrict__ Whi, const __nv_bfloat16* __restrict__ Wlo,
    const float* __restrict__ bl, const float* __restrict__ br)
{
    extern __shared__ char smem[];
    uint32_t sb = smem_u32(smem);
    int tid = threadIdx.x;
    int mat = blockIdx.y;

    const float* bias = mat ? br : bl;
    float* out = mat ? d_xr : d_xl;
    const uint4* ahi4 = (const uint4*)Ahi;
    const uint4* alo4 = (const uint4*)Alo;
    const uint4* wh4 = (const uint4*)(Whi + (size_t)mat * DIM * DIM);
    const uint4* wl4 = (const uint4*)(Wlo + (size_t)mat * DIM * DIM);

    int tb0 = blockIdx.x;
    for (int t = tid; t < 2048; t += 256) {
        int r = t >> 4, c = t & 15;
        uint32_t so = r * 256 + ((c ^ (r & 7)) << 4);
        cp16(sb + SW_HI + so, wh4 + t);
        cp16(sb + SW_LO + so, wl4 + t);
    }
    if (tb0 < NTILES) {
        int row0 = tb0 * 64;
        for (int t = tid; t < 1024; t += 256) {
            int r = t >> 4, c = t & 15;
            uint32_t so = r * 256 + ((c ^ (r & 7)) << 4);
            cp16(sb + SA_BUF + so, ahi4 + (row0 + r) * 16 + c);
            cp16(sb + SA_BUF + 16384 + so, alo4 + (row0 + r) * 16 + c);
        }
    }
    CP_COMMIT();
    CP_WAIT0();
    __syncthreads();

    int w = tid >> 5, lane = tid & 31;
    int mBase = (w >> 2) * 32;
    int nBase = (w & 3) * 32;
    int arow = lane & 15;
    int asel = lane >> 4;
    int brow_in = (lane & 7) + ((lane >> 3) & 1) * 8;
    int bsel = lane >> 4;
    int r0 = lane >> 2;
    int c2 = (lane & 3) * 2;

    int buf = 0;
    for (int tb = tb0; tb < NTILES; tb += gridDim.x) {
        int tn = tb + gridDim.x;
        if (tn < NTILES) {
            uint32_t ab = sb + SA_BUF + (buf ^ 1) * ABUF_SZ;
            int rown = tn * 64;
            for (int t = tid; t < 1024; t += 256) {
                int r = t >> 4, c = t & 15;
                uint32_t so = r * 256 + ((c ^ (r & 7)) << 4);
                cp16(ab + so, ahi4 + (rown + r) * 16 + c);
                cp16(ab + 16384 + so, alo4 + (rown + r) * 16 + c);
            }
        }
        CP_COMMIT();

        uint32_t sa_hi = sb + SA_BUF + buf * ABUF_SZ;
        uint32_t sa_lo = sa_hi + 16384;

        float acc[2][4][4];
        #pragma unroll
        for (int mt = 0; mt < 2; mt++)
            #pragma unroll
            for (int nt = 0; nt < 4; nt++)
                #pragma unroll
                for (int j = 0; j < 4; j++) acc[mt][nt][j] = 0.f;

        #pragma unroll
        for (int ks = 0; ks < 8; ks++) {
            uint32_t ah[2][4], al[2][4];
            int achunk = ks * 2 + asel;
            #pragma unroll
            for (int mt = 0; mt < 2; mt++) {
                int r = mBase + mt * 16 + arow;
                uint32_t off = r * 256 + ((achunk ^ (r & 7)) << 4);
                ldsm_x4(ah[mt], sa_hi + off);
                ldsm_x4(al[mt], sa_lo + off);
            }
            uint32_t bh[2][4], bo[2][4];
            int brow = ks * 16 + brow_in;
            #pragma unroll
            for (int nt2 = 0; nt2 < 2; nt2++) {
                int chunk = ((nBase + nt2 * 16) >> 3) + bsel;
                uint32_t off = brow * 256 + ((chunk ^ (brow & 7)) << 4);
                ldsm_x4_t(bh[nt2], sb + SW_HI + off);
                ldsm_x4_t(bo[nt2], sb + SW_LO + off);
            }
            #pragma unroll
            for (int mt = 0; mt < 2; mt++)
                #pragma unroll
                for (int nt = 0; nt < 4; nt++) {
                    const uint32_t* ph = &bh[nt >> 1][(nt & 1) * 2];
                    const uint32_t* pl = &bo[nt >> 1][(nt & 1) * 2];
                    mma16816(acc[mt][nt], ah[mt], ph);
                    mma16816(acc[mt][nt], al[mt], ph);
                    mma16816(acc[mt][nt], ah[mt], pl);
                }
        }

        int row0 = tb * 64;
        #pragma unroll
        for (int nt = 0; nt < 4; nt++) {
            int col = nBase + nt * 8 + c2;
            float2 bi = *(const float2*)(bias + col);
            #pragma unroll
            for (int mt = 0; mt < 2; mt++) {
                int g0 = row0 + mBase + mt * 16 + r0;
                float2 o0 = {acc[mt][nt][0] + bi.x, acc[mt][nt][1] + bi.y};
                *(float2*)(out + (size_t)g0 * DIM + col) = o0;
                float2 o1 = {acc[mt][nt][2] + bi.x, acc[mt][nt][3] + bi.y};
                *(float2*)(out + (size_t)(g0 + 8) * DIM + col) = o1;
            }
        }

        CP_WAIT0();
        __syncthreads();
        buf ^= 1;
    }
}

// ---------------- GATv2 aggregation: packed f32x2 math, fixed-shift softmax ----------------
__global__ __launch_bounds__(256) void k_gat(
    const float* __restrict__ xl, const float* __restrict__ xr,
    const float* __restrict__ att, const float* __restrict__ conv_bias,
    const float* __restrict__ bn_gamma, const float* __restrict__ bn_beta,
    const float* __restrict__ bn_mean, const float* __restrict__ bn_var,
    float* __restrict__ hout, int write_bf, int write_f32)
{
    int i = blockIdx.x * 8 + (threadIdx.x >> 5);
    if (i >= NODES) return;
    int lane = threadIdx.x & 31;
    int c = lane * 4;
    const char* xlb = (const char*)xl + (size_t)c * 4;

    float4 w = *(const float4*)(att + c);
    u64 w06a = pk2(0.6f * w.x, 0.6f * w.y), w06b = pk2(0.6f * w.z, 0.6f * w.w);
    u64 w04a = pk2(0.4f * w.x, 0.4f * w.y), w04b = pk2(0.4f * w.z, 0.4f * w.w);
    float4 xr4 = *(const float4*)(xr + (size_t)i * DIM + c);
    u64 X0 = pk2(xr4.x, xr4.y), X1 = pk2(xr4.z, xr4.w);

    // self loop: shift = self logit
    float4 sv = *(const float4*)(xlb + ((uint32_t)i << 9));
    u64 sva = pk2(sv.x, sv.y), svb = pk2(sv.z, sv.w);
    float m0 = hred8(pdot(sva, svb, X0, X1, w06a, w06b, w04a, w04b));
    float denom = 1.0f;
    u64 acc0 = sva, acc1 = svb;

    int beg = d_rowptr[i];
    int end = d_rowptr[i + 1];
    int j = beg;
    for (; j + 4 <= end; j += 4) {
        uint32_t s0 = d_srcs[j];
        uint32_t s1 = d_srcs[j + 1];
        uint32_t s2 = d_srcs[j + 2];
        uint32_t s3 = d_srcs[j + 3];
        float4 v0 = *(const float4*)(xlb + (s0 << 9));
        float4 v1 = *(const float4*)(xlb + (s1 << 9));
        float4 v2 = *(const float4*)(xlb + (s2 << 9));
        float4 v3 = *(const float4*)(xlb + (s3 << 9));
        u64 v0a = pk2(v0.x, v0.y), v0b = pk2(v0.z, v0.w);
        u64 v1a = pk2(v1.x, v1.y), v1b = pk2(v1.z, v1.w);
        u64 v2a = pk2(v2.x, v2.y), v2b = pk2(v2.z, v2.w);
        u64 v3a = pk2(v3.x, v3.y), v3b = pk2(v3.z, v3.w);
        float a0 = __expf(hred8(pdot(v0a, v0b, X0, X1, w06a, w06b, w04a, w04b)) - m0);
        float a1 = __expf(hred8(pdot(v1a, v1b, X0, X1, w06a, w06b, w04a, w04b)) - m0);
        float a2 = __expf(hred8(pdot(v2a, v2b, X0, X1, w06a, w06b, w04a, w04b)) - m0);
        float a3 = __expf(hred8(pdot(v3a, v3b, X0, X1, w06a, w06b, w04a, w04b)) - m0);
        denom += (a0 + a1) + (a2 + a3);
        u64 A0 = pk2(a0, a0), A1 = pk2(a1, a1), A2 = pk2(a2, a2), A3 = pk2(a3, a3);
        FMA2(acc0, v0a, A0, acc0); FMA2(acc1, v0b, A0, acc1);
        FMA2(acc0, v1a, A1, acc0); FMA2(acc1, v1b, A1, acc1);
        FMA2(acc0, v2a, A2, acc0); FMA2(acc1, v2b, A2, acc1);
        FMA2(acc0, v3a, A3, acc0); FMA2(acc1, v3b, A3, acc1);
    }
    for (; j < end; j++) {
        uint32_t s0 = d_srcs[j];
        float4 v0 = *(const float4*)(xlb + (s0 << 9));
        u64 v0a = pk2(v0.x, v0.y), v0b = pk2(v0.z, v0.w);
        float a0 = __expf(hred8(pdot(v0a, v0b, X0, X1, w06a, w06b, w04a, w04b)) - m0);
        denom += a0;
        u64 A0 = pk2(a0, a0);
        FMA2(acc0, v0a, A0, acc0);
        FMA2(acc1, v0b, A0, acc1);
    }

    float inv = 1.0f / denom;
    float accx, accy, accz, accw;
    upk2(acc0, accx, accy);
    upk2(acc1, accz, accw);
    float4 bias = *(const float4*)(conv_bias + c);
    float4 ga = *(const float4*)(bn_gamma + c);
    float4 be = *(const float4*)(bn_beta + c);
    float4 mu = *(const float4*)(bn_mean + c);
    float4 va = *(const float4*)(bn_var + c);
    float4 o;
    o.x = fmaxf((accx * inv + bias.x - mu.x) * rsqrtf(va.x + BN_EPS) * ga.x + be.x, 0.f);
    o.y = fmaxf((accy * inv + bias.y - mu.y) * rsqrtf(va.y + BN_EPS) * ga.y + be.y, 0.f);
    o.z = fmaxf((accz * inv + bias.z - mu.z) * rsqrtf(va.z + BN_EPS) * ga.z + be.z, 0.f);
    o.w = fmaxf((accw * inv + bias.w - mu.w) * rsqrtf(va.w + BN_EPS) * ga.w + be.w, 0.f);

    if (write_f32) *(float4*)(hout + (size_t)i * DIM + c) = o;
    if (write_bf) {
        __nv_bfloat16 hx = __float2bfloat16(o.x);
        __nv_bfloat16 hy = __float2bfloat16(o.y);
        __nv_bfloat16 hz = __float2bfloat16(o.z);
        __nv_bfloat16 hw = __float2bfloat16(o.w);
        __nv_bfloat162* ph = (__nv_bfloat162*)(d_hhi + (size_t)i * DIM + c);
        ph[0] = __nv_bfloat162(hx, hy);
        ph[1] = __nv_bfloat162(hz, hw);
        __nv_bfloat162* pl = (__nv_bfloat162*)(d_hlo + (size_t)i * DIM + c);
        pl[0] = __nv_bfloat162(__float2bfloat16(o.x - __bfloat162float(hx)),
                               __float2bfloat16(o.y - __bfloat162float(hy)));
        pl[1] = __nv_bfloat162(__float2bfloat16(o.z - __bfloat162float(hz)),
                               __float2bfloat16(o.w - __bfloat162float(hw)));
    }
}

// ---------------- mean pool (batch sorted) + MLP 128->64->2 ----------------
__global__ void k_pool_mlp(
    const float* __restrict__ h, const int* __restrict__ batch,
    const float* __restrict__ W1, const float* __restrict__ b1,
    const float* __restrict__ W2, const float* __restrict__ b2,
    float* __restrict__ out)
{
    __shared__ float p[DIM];
    __shared__ float hid[64];
    int g = blockIdx.x;
    int t = threadIdx.x;

    int lo = 0, hi = NODES;
    while (lo < hi) { int mid = (lo + hi) >> 1; if (batch[mid] < g) lo = mid + 1; else hi = mid; }
    int beg = lo;
    hi = NODES;
    while (lo < hi) { int mid = (lo + hi) >> 1; if (batch[mid] < g + 1) lo = mid + 1; else hi = mid; }
    int end = lo;

    float sum = 0.f;
    for (int n = beg; n < end; n++) sum += h[(size_t)n * DIM + t];
    float cnt = (float)(end - beg);
    p[t] = sum / fmaxf(cnt, 1.0f);
    __syncthreads();

    if (t < 64) {
        float a = b1[t];
        #pragma unroll 8
        for (int k = 0; k < DIM; k++) a = fmaf(p[k], W1[k * 64 + t], a);
        hid[t] = fmaxf(a, 0.f);
    }
    __syncthreads();

    if (t < 2) {
        float a = b2[t];
        #pragma unroll 8
        for (int k = 0; k < 64; k++) a = fmaf(hid[k], W2[k * 2 + t], a);
        out[g * 2 + t] = a;
    }
}

// ---------------- launch ----------------
extern "C" void kernel_launch(void* const* d_in, const int* in_sizes, int n_in,
                              void* d_out, int out_size)
{
    const float* x     = (const float*)d_in[0];
    const int*   ei    = (const int*)d_in[1];
    const int*   batch = (const int*)d_in[2];
    const float* Wl    = (const float*)d_in[3];
    const float* bl    = (const float*)d_in[4];
    const float* Wr    = (const float*)d_in[5];
    const float* br    = (const float*)d_in[6];
    const float* att   = (const float*)d_in[7];
    const float* cb    = (const float*)d_in[8];
    const float* bng   = (const float*)d_in[9];
    const float* bnb   = (const float*)d_in[10];
    const float* bnm   = (const float*)d_in[11];
    const float* bnv   = (const float*)d_in[12];
    const float* W1    = (const float*)d_in[13];
    const float* b1    = (const float*)d_in[14];
    const float* W2    = (const float*)d_in[15];
    const float* b2    = (const float*)d_in[16];
    float* out = (float*)d_out;

    float *h0, *xl, *xr;
    __nv_bfloat16 *hhi, *hlo, *whi, *wlo;
    cudaGetSymbolAddress((void**)&h0, d_h0);
    cudaGetSymbolAddress((void**)&xl, d_xl);
    cudaGetSymbolAddress((void**)&xr, d_xr);
    cudaGetSymbolAddress((void**)&hhi, d_hhi);
    cudaGetSymbolAddress((void**)&hlo, d_hlo);
    cudaGetSymbolAddress((void**)&whi, d_whi);
    cudaGetSymbolAddress((void**)&wlo, d_wlo);

    static int smem_set = 0;
    if (!smem_set) {
        cudaFuncSetAttribute(k_gemm_tc, cudaFuncAttributeMaxDynamicSharedMemorySize, GSMEM);
        smem_set = 1;
    }

    dim3 ggrid(74, 2);

    // order: launch index 3 (ncu capture slot) = k_gat_probe (new packed loop)
    k_convx_zero<<<(NODES * DIM + 255) / 256, 256>>>(x);             // 0
    k_hist_cw<<<HIST_BLOCKS + 6, 256>>>(ei, Wl, Wr);                 // 1
    k_scan<<<1, 1024>>>();                                           // 2
    k_gat_probe<<<(PROBE_NODES + 7) / 8, 256>>>(x, att);             // 3  <-- profiled
    k_gemm_tc<<<ggrid, 256, GSMEM>>>(hhi, hlo, whi, wlo, bl, br);    // 4
    k_scatter<<<(EDGES + 255) / 256, 256>>>(ei);                     // 5

    for (int l = 0; l < 3; l++) {
        if (l > 0) {
            k_gemm_tc<<<ggrid, 256, GSMEM>>>(
                hhi, hlo,
                whi + (size_t)l * 2 * DIM * DIM, wlo + (size_t)l * 2 * DIM * DIM,
                bl + l * DIM, br + l * DIM);
        }
        k_gat<<<NODES / 8, 256>>>(xl, xr,
                                  att + l * DIM, cb + l * DIM,
                                  bng + l * DIM, bnb + l * DIM,
                                  bnm + l * DIM, bnv + l * DIM,
                                  h0, (l < 2) ? 1 : 0, (l == 2) ? 1 : 0);
    }

    k_pool_mlp<<<GRAPHS, 128>>>(h0, batch, W1, b1, W2, b2, out);
}

// round 12
// speedup vs baseline: 1.0007x; 1.0007x over previous
#include <cuda_runtime.h>
#include <cuda_bf16.h>
#include <cstdint>

#define NODES 40000
#define EDGES 640000
#define DIM 128
#define GRAPHS 512
#define NEG_SLOPE 0.2f
#define BN_EPS 1e-5f

// ---------------- scratch (no allocations allowed) ----------------
__device__ float d_h0[NODES * DIM];
__device__ float d_xl[NODES * DIM];
__device__ float d_xr[NODES * DIM];
__device__ __nv_bfloat16 d_hhi[NODES * DIM];
__device__ __nv_bfloat16 d_hlo[NODES * DIM];
__device__ __nv_bfloat16 d_whi[3 * 2 * DIM * DIM];
__device__ __nv_bfloat16 d_wlo[3 * 2 * DIM * DIM];
__device__ int d_deg[NODES];
__device__ int d_rowptr[NODES + 1];
__device__ int d_cursor[NODES];
__device__ int d_srcs[EDGES];

__device__ __forceinline__ uint32_t smem_u32(const void* p) {
    uint32_t a;
    asm("{ .reg .u64 t; cvta.to.shared.u64 t, %1; cvt.u32.u64 %0, t; }" : "=r"(a) : "l"(p));
    return a;
}
__device__ __forceinline__ void ldsm_x4(uint32_t* r, uint32_t addr) {
    asm volatile("ldmatrix.sync.aligned.m8n8.x4.shared.b16 {%0,%1,%2,%3}, [%4];"
                 : "=r"(r[0]), "=r"(r[1]), "=r"(r[2]), "=r"(r[3]) : "r"(addr));
}
__device__ __forceinline__ void ldsm_x4_t(uint32_t* r, uint32_t addr) {
    asm volatile("ldmatrix.sync.aligned.m8n8.x4.trans.shared.b16 {%0,%1,%2,%3}, [%4];"
                 : "=r"(r[0]), "=r"(r[1]), "=r"(r[2]), "=r"(r[3]) : "r"(addr));
}
__device__ __forceinline__ void mma16816(float* c, const uint32_t* a, const uint32_t* b) {
    asm volatile(
        "mma.sync.aligned.m16n8k16.row.col.f32.bf16.bf16.f32 "
        "{%0,%1,%2,%3}, {%4,%5,%6,%7}, {%8,%9}, {%0,%1,%2,%3};"
        : "+f"(c[0]), "+f"(c[1]), "+f"(c[2]), "+f"(c[3])
        : "r"(a[0]), "r"(a[1]), "r"(a[2]), "r"(a[3]), "r"(b[0]), "r"(b[1]));
}
__device__ __forceinline__ void cp16(uint32_t saddr, const void* gaddr) {
    asm volatile("cp.async.cg.shared.global [%0], [%1], 16;" :: "r"(saddr), "l"(gaddr));
}
#define CP_COMMIT() asm volatile("cp.async.commit_group;" ::: "memory")
#define CP_WAIT0()  asm volatile("cp.async.wait_group 0;" ::: "memory")

// ---------------- fused: convert x to bf16 hi/lo + zero deg ----------------
__global__ void k_convx_zero(const float* __restrict__ x) {
    int i = blockIdx.x * blockDim.x + threadIdx.x;
    if (i < NODES * DIM) {
        float v = x[i];
        __nv_bfloat16 h = __float2bfloat16(v);
        d_hhi[i] = h;
        d_hlo[i] = __float2bfloat16(v - __bfloat162float(h));
    }
    if (i < NODES) d_deg[i] = 0;
}

// ---------------- fused: degree histogram + convert weights ----------------
#define HIST_BLOCKS (EDGES / 256)
__global__ void k_hist_cw(const int* __restrict__ ei,
                          const float* __restrict__ Wl, const float* __restrict__ Wr) {
    if (blockIdx.x < HIST_BLOCKS) {
        int e = blockIdx.x * blockDim.x + threadIdx.x;
        atomicAdd(&d_deg[ei[EDGES + e]], 1);
    } else {
        int b = blockIdx.x - HIST_BLOCKS;
        int l = b >> 1, m = b & 1;
        const float* W = (m ? Wr : Wl) + (size_t)l * DIM * DIM;
        __nv_bfloat16* oh = d_whi + (size_t)(l * 2 + m) * DIM * DIM;
        __nv_bfloat16* ol = d_wlo + (size_t)(l * 2 + m) * DIM * DIM;
        for (int t = threadIdx.x; t < DIM * DIM; t += blockDim.x) {
            float v = W[t];
            __nv_bfloat16 h = __float2bfloat16(v);
            oh[t] = h;
            ol[t] = __float2bfloat16(v - __bfloat162float(h));
        }
    }
}

#define SCAN_CH 40
__global__ void k_scan() {
    __shared__ int ws[32];
    int t = threadIdx.x, lane = t & 31, wid = t >> 5;
    int base = t * SCAN_CH;
    int s = 0;
    #pragma unroll 4
    for (int k = 0; k < SCAN_CH; k++) {
        int idx = base + k;
        if (idx < NODES) s += d_deg[idx];
    }
    int x = s;
    #pragma unroll
    for (int o = 1; o < 32; o <<= 1) {
        int y = __shfl_up_sync(0xffffffffu, x, o);
        if (lane >= o) x += y;
    }
    if (lane == 31) ws[wid] = x;
    __syncthreads();
    if (wid == 0) {
        int sv = ws[lane], sx = sv;
        #pragma unroll
        for (int o = 1; o < 32; o <<= 1) {
            int y = __shfl_up_sync(0xffffffffu, sx, o);
            if (lane >= o) sx += y;
        }
        ws[lane] = sx - sv;
    }
    __syncthreads();
    int run = ws[wid] + x - s;
    #pragma unroll 4
    for (int k = 0; k < SCAN_CH; k++) {
        int idx = base + k;
        if (idx < NODES) {
            int dg = d_deg[idx];
            d_rowptr[idx] = run;
            d_cursor[idx] = run;
            run += dg;
        }
    }
    if (t == 1023) d_rowptr[NODES] = run;
}
__global__ void k_scatter(const int* __restrict__ ei) {
    int e = blockIdx.x * blockDim.x + threadIdx.x;
    if (e < EDGES) {
        int dst = ei[EDGES + e];
        int pos = atomicAdd(&d_cursor[dst], 1);
        d_srcs[pos] = ei[e];
    }
}

// ---------------- persistent HMMA dual GEMM (R8 split version) ----------------
#define SW_HI 0
#define SW_LO 32768
#define SA_BUF 65536
#define ABUF_SZ 32768
#define GSMEM 131072
#define NTILES (NODES / 64)

__global__ __launch_bounds__(256, 1) void k_gemm_tc(
    const __nv_bfloat16* __restrict__ Ahi, const __nv_bfloat16* __restrict__ Alo,
    const __nv_bfloat16* __restrict__ Whi, const __nv_bfloat16* __restrict__ Wlo,
    const float* __restrict__ bl, const float* __restrict__ br)
{
    extern __shared__ char smem[];
    uint32_t sb = smem_u32(smem);
    int tid = threadIdx.x;
    int mat = blockIdx.y;

    const float* bias = mat ? br : bl;
    float* out = mat ? d_xr : d_xl;
    const uint4* ahi4 = (const uint4*)Ahi;
    const uint4* alo4 = (const uint4*)Alo;
    const uint4* wh4 = (const uint4*)(Whi + (size_t)mat * DIM * DIM);
    const uint4* wl4 = (const uint4*)(Wlo + (size_t)mat * DIM * DIM);

    int tb0 = blockIdx.x;
    for (int t = tid; t < 2048; t += 256) {
        int r = t >> 4, c = t & 15;
        uint32_t so = r * 256 + ((c ^ (r & 7)) << 4);
        cp16(sb + SW_HI + so, wh4 + t);
        cp16(sb + SW_LO + so, wl4 + t);
    }
    if (tb0 < NTILES) {
        int row0 = tb0 * 64;
        for (int t = tid; t < 1024; t += 256) {
            int r = t >> 4, c = t & 15;
            uint32_t so = r * 256 + ((c ^ (r & 7)) << 4);
            cp16(sb + SA_BUF + so, ahi4 + (row0 + r) * 16 + c);
            cp16(sb + SA_BUF + 16384 + so, alo4 + (row0 + r) * 16 + c);
        }
    }
    CP_COMMIT();
    CP_WAIT0();
    __syncthreads();

    int w = tid >> 5, lane = tid & 31;
    int mBase = (w >> 2) * 32;
    int nBase = (w & 3) * 32;
    int arow = lane & 15;
    int asel = lane >> 4;
    int brow_in = (lane & 7) + ((lane >> 3) & 1) * 8;
    int bsel = lane >> 4;
    int r0 = lane >> 2;
    int c2 = (lane & 3) * 2;

    int buf = 0;
    for (int tb = tb0; tb < NTILES; tb += gridDim.x) {
        int tn = tb + gridDim.x;
        if (tn < NTILES) {
            uint32_t ab = sb + SA_BUF + (buf ^ 1) * ABUF_SZ;
            int rown = tn * 64;
            for (int t = tid; t < 1024; t += 256) {
                int r = t >> 4, c = t & 15;
                uint32_t so = r * 256 + ((c ^ (r & 7)) << 4);
                cp16(ab + so, ahi4 + (rown + r) * 16 + c);
                cp16(ab + 16384 + so, alo4 + (rown + r) * 16 + c);
            }
        }
        CP_COMMIT();

        uint32_t sa_hi = sb + SA_BUF + buf * ABUF_SZ;
        uint32_t sa_lo = sa_hi + 16384;

        float acc[2][4][4];
        #pragma unroll
        for (int mt = 0; mt < 2; mt++)
            #pragma unroll
            for (int nt = 0; nt < 4; nt++)
                #pragma unroll
                for (int j = 0; j < 4; j++) acc[mt][nt][j] = 0.f;

        #pragma unroll
        for (int ks = 0; ks < 8; ks++) {
            uint32_t ah[2][4], al[2][4];
            int achunk = ks * 2 + asel;
            #pragma unroll
            for (int mt = 0; mt < 2; mt++) {
                int r = mBase + mt * 16 + arow;
                uint32_t off = r * 256 + ((achunk ^ (r & 7)) << 4);
                ldsm_x4(ah[mt], sa_hi + off);
                ldsm_x4(al[mt], sa_lo + off);
            }
            uint32_t bh[2][4], bo[2][4];
            int brow = ks * 16 + brow_in;
            #pragma unroll
            for (int nt2 = 0; nt2 < 2; nt2++) {
                int chunk = ((nBase + nt2 * 16) >> 3) + bsel;
                uint32_t off = brow * 256 + ((chunk ^ (brow & 7)) << 4);
                ldsm_x4_t(bh[nt2], sb + SW_HI + off);
                ldsm_x4_t(bo[nt2], sb + SW_LO + off);
            }
            #pragma unroll
            for (int mt = 0; mt < 2; mt++)
                #pragma unroll
                for (int nt = 0; nt < 4; nt++) {
                    const uint32_t* ph = &bh[nt >> 1][(nt & 1) * 2];
                    const uint32_t* pl = &bo[nt >> 1][(nt & 1) * 2];
                    mma16816(acc[mt][nt], ah[mt], ph);
                    mma16816(acc[mt][nt], al[mt], ph);
                    mma16816(acc[mt][nt], ah[mt], pl);
                }
        }

        int row0 = tb * 64;
        #pragma unroll
        for (int nt = 0; nt < 4; nt++) {
            int col = nBase + nt * 8 + c2;
            float2 bi = *(const float2*)(bias + col);
            #pragma unroll
            for (int mt = 0; mt < 2; mt++) {
                int g0 = row0 + mBase + mt * 16 + r0;
                float2 o0 = {acc[mt][nt][0] + bi.x, acc[mt][nt][1] + bi.y};
                *(float2*)(out + (size_t)g0 * DIM + col) = o0;
                float2 o1 = {acc[mt][nt][2] + bi.x, acc[mt][nt][3] + bi.y};
                *(float2*)(out + (size_t)(g0 + 8) * DIM + col) = o1;
            }
        }

        CP_WAIT0();
        __syncthreads();
        buf ^= 1;
    }
}

// ---------------- GATv2 aggregation: scalar, 4-edge unroll, high occupancy ----------------
__device__ __forceinline__ float leaky_dot(float4 v, float4 x, float4 w) {
    float zx = v.x + x.x, zy = v.y + x.y, zz = v.z + x.z, zw = v.w + x.w;
    zx = fmaxf(zx, NEG_SLOPE * zx);
    zy = fmaxf(zy, NEG_SLOPE * zy);
    zz = fmaxf(zz, NEG_SLOPE * zz);
    zw = fmaxf(zw, NEG_SLOPE * zw);
    return zx * w.x + zy * w.y + zz * w.z + zw * w.w;
}
__device__ __forceinline__ float hred8(float d) {
    d += __shfl_xor_sync(0xffffffffu, d, 1);
    d += __shfl_xor_sync(0xffffffffu, d, 2);
    d += __shfl_xor_sync(0xffffffffu, d, 4);
    return d;
}

__global__ __launch_bounds__(256, 6) void k_gat(
    const float* __restrict__ xl, const float* __restrict__ xr,
    const float* __restrict__ att, const float* __restrict__ conv_bias,
    const float* __restrict__ bn_gamma, const float* __restrict__ bn_beta,
    const float* __restrict__ bn_mean, const float* __restrict__ bn_var,
    float* __restrict__ hout, int write_bf, int write_f32)
{
    int i = blockIdx.x * 8 + (threadIdx.x >> 5);
    if (i >= NODES) return;
    int lane = threadIdx.x & 31;
    int c = lane * 4;
    const char* xlb = (const char*)xl + (size_t)c * 4;

    float4 w   = *(const float4*)(att + c);
    float4 xr4 = *(const float4*)(xr + (size_t)i * DIM + c);

    float4 xls = *(const float4*)(xlb + ((uint32_t)i << 9));
    float m0 = hred8(leaky_dot(xls, xr4, w));
    float denom = 1.0f;
    float4 acc = xls;

    int beg = d_rowptr[i];
    int end = d_rowptr[i + 1];
    int j = beg;
    for (; j + 4 <= end; j += 4) {
        uint32_t s0 = d_srcs[j];
        uint32_t s1 = d_srcs[j + 1];
        uint32_t s2 = d_srcs[j + 2];
        uint32_t s3 = d_srcs[j + 3];
        float4 v0 = *(const float4*)(xlb + (s0 << 9));
        float4 v1 = *(const float4*)(xlb + (s1 << 9));
        float4 v2 = *(const float4*)(xlb + (s2 << 9));
        float4 v3 = *(const float4*)(xlb + (s3 << 9));
        float d0 = hred8(leaky_dot(v0, xr4, w));
        float d1 = hred8(leaky_dot(v1, xr4, w));
        float d2 = hred8(leaky_dot(v2, xr4, w));
        float d3 = hred8(leaky_dot(v3, xr4, w));
        float a0 = __expf(d0 - m0);
        float a1 = __expf(d1 - m0);
        float a2 = __expf(d2 - m0);
        float a3 = __expf(d3 - m0);
        denom += (a0 + a1) + (a2 + a3);
        acc.x += (a0 * v0.x + a1 * v1.x) + (a2 * v2.x + a3 * v3.x);
        acc.y += (a0 * v0.y + a1 * v1.y) + (a2 * v2.y + a3 * v3.y);
        acc.z += (a0 * v0.z + a1 * v1.z) + (a2 * v2.z + a3 * v3.z);
        acc.w += (a0 * v0.w + a1 * v1.w) + (a2 * v2.w + a3 * v3.w);
    }
    for (; j < end; j++) {
        uint32_t s0 = d_srcs[j];
        float4 v0 = *(const float4*)(xlb + (s0 << 9));
        float a0 = __expf(hred8(leaky_dot(v0, xr4, w)) - m0);
        denom += a0;
        acc.x += a0 * v0.x;
        acc.y += a0 * v0.y;
        acc.z += a0 * v0.z;
        acc.w += a0 * v0.w;
    }

    float inv = 1.0f / denom;
    float4 bias = *(const float4*)(conv_bias + c);
    float4 ga = *(const float4*)(bn_gamma + c);
    float4 be = *(const float4*)(bn_beta + c);
    float4 mu = *(const float4*)(bn_mean + c);
    float4 va = *(const float4*)(bn_var + c);
    float4 o;
    o.x = fmaxf((acc.x * inv + bias.x - mu.x) * rsqrtf(va.x + BN_EPS) * ga.x + be.x, 0.f);
    o.y = fmaxf((acc.y * inv + bias.y - mu.y) * rsqrtf(va.y + BN_EPS) * ga.y + be.y, 0.f);
    o.z = fmaxf((acc.z * inv + bias.z - mu.z) * rsqrtf(va.z + BN_EPS) * ga.z + be.z, 0.f);
    o.w = fmaxf((acc.w * inv + bias.w - mu.w) * rsqrtf(va.w + BN_EPS) * ga.w + be.w, 0.f);

    if (write_f32) *(float4*)(hout + (size_t)i * DIM + c) = o;
    if (write_bf) {
        __nv_bfloat16 hx = __float2bfloat16(o.x);
        __nv_bfloat16 hy = __float2bfloat16(o.y);
        __nv_bfloat16 hz = __float2bfloat16(o.z);
        __nv_bfloat16 hw = __float2bfloat16(o.w);
        __nv_bfloat162* ph = (__nv_bfloat162*)(d_hhi + (size_t)i * DIM + c);
        ph[0] = __nv_bfloat162(hx, hy);
        ph[1] = __nv_bfloat162(hz, hw);
        __nv_bfloat162* pl = (__nv_bfloat162*)(d_hlo + (size_t)i * DIM + c);
        pl[0] = __nv_bfloat162(__float2bfloat16(o.x - __bfloat162float(hx)),
                               __float2bfloat16(o.y - __bfloat162float(hy)));
        pl[1] = __nv_bfloat162(__float2bfloat16(o.z - __bfloat162float(hz)),
                               __float2bfloat16(o.w - __bfloat162float(hw)));
    }
}

// ---------------- mean pool (batch sorted) + MLP 128->64->2 ----------------
__global__ void k_pool_mlp(
    const float* __restrict__ h, const int* __restrict__ batch,
    const float* __restrict__ W1, const float* __restrict__ b1,
    const float* __restrict__ W2, const float* __restrict__ b2,
    float* __restrict__ out)
{
    __shared__ float p[DIM];
    __shared__ float hid[64];
    int g = blockIdx.x;
    int t = threadIdx.x;

    int lo = 0, hi = NODES;
    while (lo < hi) { int mid = (lo + hi) >> 1; if (batch[mid] < g) lo = mid + 1; else hi = mid; }
    int beg = lo;
    hi = NODES;
    while (lo < hi) { int mid = (lo + hi) >> 1; if (batch[mid] < g + 1) lo = mid + 1; else hi = mid; }
    int end = lo;

    float sum = 0.f;
    for (int n = beg; n < end; n++) sum += h[(size_t)n * DIM + t];
    float cnt = (float)(end - beg);
    p[t] = sum / fmaxf(cnt, 1.0f);
    __syncthreads();

    if (t < 64) {
        float a = b1[t];
        #pragma unroll 8
        for (int k = 0; k < DIM; k++) a = fmaf(p[k], W1[k * 64 + t], a);
        hid[t] = fmaxf(a, 0.f);
    }
    __syncthreads();

    if (t < 2) {
        float a = b2[t];
        #pragma unroll 8
        for (int k = 0; k < 64; k++) a = fmaf(hid[k], W2[k * 2 + t], a);
        out[g * 2 + t] = a;
    }
}

// ---------------- launch ----------------
extern "C" void kernel_launch(void* const* d_in, const int* in_sizes, int n_in,
                              void* d_out, int out_size)
{
    const float* x     = (const float*)d_in[0];
    const int*   ei    = (const int*)d_in[1];
    const int*   batch = (const int*)d_in[2];
    const float* Wl    = (const float*)d_in[3];
    const float* bl    = (const float*)d_in[4];
    const float* Wr    = (const float*)d_in[5];
    const float* br    = (const float*)d_in[6];
    const float* att   = (const float*)d_in[7];
    const float* cb    = (const float*)d_in[8];
    const float* bng   = (const float*)d_in[9];
    const float* bnb   = (const float*)d_in[10];
    const float* bnm   = (const float*)d_in[11];
    const float* bnv   = (const float*)d_in[12];
    const float* W1    = (const float*)d_in[13];
    const float* b1    = (const float*)d_in[14];
    const float* W2    = (const float*)d_in[15];
    const float* b2    = (const float*)d_in[16];
    float* out = (float*)d_out;

    float *h0, *xl, *xr;
    __nv_bfloat16 *hhi, *hlo, *whi, *wlo;
    cudaGetSymbolAddress((void**)&h0, d_h0);
    cudaGetSymbolAddress((void**)&xl, d_xl);
    cudaGetSymbolAddress((void**)&xr, d_xr);
    cudaGetSymbolAddress((void**)&hhi, d_hhi);
    cudaGetSymbolAddress((void**)&hlo, d_hlo);
    cudaGetSymbolAddress((void**)&whi, d_whi);
    cudaGetSymbolAddress((void**)&wlo, d_wlo);

    static int smem_set = 0;
    if (!smem_set) {
        cudaFuncSetAttribute(k_gemm_tc, cudaFuncAttributeMaxDynamicSharedMemorySize, GSMEM);
        smem_set = 1;
    }

    dim3 ggrid(74, 2);

    // order: launch index 3 (ncu capture slot) = k_gemm_tc layer 0
    k_convx_zero<<<(NODES * DIM + 255) / 256, 256>>>(x);             // 0
    k_hist_cw<<<HIST_BLOCKS + 6, 256>>>(ei, Wl, Wr);                 // 1
    k_scan<<<1, 1024>>>();                                           // 2
    k_gemm_tc<<<ggrid, 256, GSMEM>>>(hhi, hlo, whi, wlo, bl, br);    // 3  <-- profiled
    k_scatter<<<(EDGES + 255) / 256, 256>>>(ei);                     // 4

    for (int l = 0; l < 3; l++) {
        if (l > 0) {
            k_gemm_tc<<<ggrid, 256, GSMEM>>>(
                hhi, hlo,
                whi + (size_t)l * 2 * DIM * DIM, wlo + (size_t)l * 2 * DIM * DIM,
                bl + l * DIM, br + l * DIM);
        }
        k_gat<<<NODES / 8, 256>>>(xl, xr,
                                  att + l * DIM, cb + l * DIM,
                                  bng + l * DIM, bnb + l * DIM,
                                  bnm + l * DIM, bnv + l * DIM,
                                  h0, (l < 2) ? 1 : 0, (l == 2) ? 1 : 0);
    }

    k_pool_mlp<<<GRAPHS, 128>>>(h0, batch, W1, b1, W2, b2, out);
}

// round 13
// speedup vs baseline: 1.0271x; 1.0263x over previous
#include <cuda_runtime.h>
#include <cuda_bf16.h>
#include <cstdint>

#define NODES 40000
#define EDGES 640000
#define DIM 128
#define GRAPHS 512
#define NEG_SLOPE 0.2f
#define BN_EPS 1e-5f
#define LOG2E 1.4426950408889634f

// ---------------- scratch (no allocations allowed) ----------------
__device__ float d_h0[NODES * DIM];
__device__ float d_xl[NODES * DIM];
__device__ float d_xr[NODES * DIM];
__device__ __nv_bfloat16 d_hhi[NODES * DIM];
__device__ __nv_bfloat16 d_hlo[NODES * DIM];
__device__ __nv_bfloat16 d_whi[3 * 2 * DIM * DIM];
__device__ __nv_bfloat16 d_wlo[3 * 2 * DIM * DIM];
__device__ int d_deg[NODES];
__device__ int d_rowptr[NODES + 1];
__device__ int d_cursor[NODES];
__device__ int d_srcs[EDGES];

__device__ __forceinline__ uint32_t smem_u32(const void* p) {
    uint32_t a;
    asm("{ .reg .u64 t; cvta.to.shared.u64 t, %1; cvt.u32.u64 %0, t; }" : "=r"(a) : "l"(p));
    return a;
}
__device__ __forceinline__ void ldsm_x4(uint32_t* r, uint32_t addr) {
    asm volatile("ldmatrix.sync.aligned.m8n8.x4.shared.b16 {%0,%1,%2,%3}, [%4];"
                 : "=r"(r[0]), "=r"(r[1]), "=r"(r[2]), "=r"(r[3]) : "r"(addr));
}
__device__ __forceinline__ void ldsm_x4_t(uint32_t* r, uint32_t addr) {
    asm volatile("ldmatrix.sync.aligned.m8n8.x4.trans.shared.b16 {%0,%1,%2,%3}, [%4];"
                 : "=r"(r[0]), "=r"(r[1]), "=r"(r[2]), "=r"(r[3]) : "r"(addr));
}
__device__ __forceinline__ void mma16816(float* c, const uint32_t* a, const uint32_t* b) {
    asm volatile(
        "mma.sync.aligned.m16n8k16.row.col.f32.bf16.bf16.f32 "
        "{%0,%1,%2,%3}, {%4,%5,%6,%7}, {%8,%9}, {%0,%1,%2,%3};"
        : "+f"(c[0]), "+f"(c[1]), "+f"(c[2]), "+f"(c[3])
        : "r"(a[0]), "r"(a[1]), "r"(a[2]), "r"(a[3]), "r"(b[0]), "r"(b[1]));
}
__device__ __forceinline__ void cp16(uint32_t saddr, const void* gaddr) {
    asm volatile("cp.async.cg.shared.global [%0], [%1], 16;" :: "r"(saddr), "l"(gaddr));
}
#define CP_COMMIT() asm volatile("cp.async.commit_group;" ::: "memory")
#define CP_WAIT0()  asm volatile("cp.async.wait_group 0;" ::: "memory")

// ---------------- fused: convert x to bf16 hi/lo + zero deg ----------------
__global__ void k_convx_zero(const float* __restrict__ x) {
    int i = blockIdx.x * blockDim.x + threadIdx.x;
    if (i < NODES * DIM) {
        float v = x[i];
        __nv_bfloat16 h = __float2bfloat16(v);
        d_hhi[i] = h;
        d_hlo[i] = __float2bfloat16(v - __bfloat162float(h));
    }
    if (i < NODES) d_deg[i] = 0;
}

// ---------------- fused: degree histogram + convert weights ----------------
#define HIST_BLOCKS (EDGES / 256)
__global__ void k_hist_cw(const int* __restrict__ ei,
                          const float* __restrict__ Wl, const float* __restrict__ Wr) {
    if (blockIdx.x < HIST_BLOCKS) {
        int e = blockIdx.x * blockDim.x + threadIdx.x;
        atomicAdd(&d_deg[ei[EDGES + e]], 1);
    } else {
        int b = blockIdx.x - HIST_BLOCKS;
        int l = b >> 1, m = b & 1;
        const float* W = (m ? Wr : Wl) + (size_t)l * DIM * DIM;
        __nv_bfloat16* oh = d_whi + (size_t)(l * 2 + m) * DIM * DIM;
        __nv_bfloat16* ol = d_wlo + (size_t)(l * 2 + m) * DIM * DIM;
        for (int t = threadIdx.x; t < DIM * DIM; t += blockDim.x) {
            float v = W[t];
            __nv_bfloat16 h = __float2bfloat16(v);
            oh[t] = h;
            ol[t] = __float2bfloat16(v - __bfloat162float(h));
        }
    }
}

#define SCAN_CH 40
__global__ void k_scan() {
    __shared__ int ws[32];
    int t = threadIdx.x, lane = t & 31, wid = t >> 5;
    int base = t * SCAN_CH;
    int s = 0;
    #pragma unroll 4
    for (int k = 0; k < SCAN_CH; k++) {
        int idx = base + k;
        if (idx < NODES) s += d_deg[idx];
    }
    int x = s;
    #pragma unroll
    for (int o = 1; o < 32; o <<= 1) {
        int y = __shfl_up_sync(0xffffffffu, x, o);
        if (lane >= o) x += y;
    }
    if (lane == 31) ws[wid] = x;
    __syncthreads();
    if (wid == 0) {
        int sv = ws[lane], sx = sv;
        #pragma unroll
        for (int o = 1; o < 32; o <<= 1) {
            int y = __shfl_up_sync(0xffffffffu, sx, o);
            if (lane >= o) sx += y;
        }
        ws[lane] = sx - sv;
    }
    __syncthreads();
    int run = ws[wid] + x - s;
    #pragma unroll 4
    for (int k = 0; k < SCAN_CH; k++) {
        int idx = base + k;
        if (idx < NODES) {
            int dg = d_deg[idx];
            d_rowptr[idx] = run;
            d_cursor[idx] = run;
            run += dg;
        }
    }
    if (t == 1023) d_rowptr[NODES] = run;
}
__global__ void k_scatter(const int* __restrict__ ei) {
    int e = blockIdx.x * blockDim.x + threadIdx.x;
    if (e < EDGES) {
        int dst = ei[EDGES + e];
        int pos = atomicAdd(&d_cursor[dst], 1);
        d_srcs[pos] = ei[e];
    }
}

// ---- persistent HMMA dual GEMM, W resident, cp.async A pipe, 512 threads / 16 warps ----
#define SW_HI 0
#define SW_LO 32768
#define SA_BUF 65536
#define ABUF_SZ 32768
#define GSMEM 131072
#define NTILES (NODES / 64)

__global__ __launch_bounds__(512, 1) void k_gemm_tc(
    const __nv_bfloat16* __restrict__ Ahi, const __nv_bfloat16* __restrict__ Alo,
    const __nv_bfloat16* __restrict__ Whi, const __nv_bfloat16* __restrict__ Wlo,
    const float* __restrict__ bl, const float* __restrict__ br)
{
    extern __shared__ char smem[];
    uint32_t sb = smem_u32(smem);
    int tid = threadIdx.x;
    int mat = blockIdx.y;

    const float* bias = mat ? br : bl;
    float* out = mat ? d_xr : d_xl;
    const uint4* ahi4 = (const uint4*)Ahi;
    const uint4* alo4 = (const uint4*)Alo;
    const uint4* wh4 = (const uint4*)(Whi + (size_t)mat * DIM * DIM);
    const uint4* wl4 = (const uint4*)(Wlo + (size_t)mat * DIM * DIM);

    int tb0 = blockIdx.x;
    for (int t = tid; t < 2048; t += 512) {
        int r = t >> 4, c = t & 15;
        uint32_t so = r * 256 + ((c ^ (r & 7)) << 4);
        cp16(sb + SW_HI + so, wh4 + t);
        cp16(sb + SW_LO + so, wl4 + t);
    }
    if (tb0 < NTILES) {
        int row0 = tb0 * 64;
        for (int t = tid; t < 1024; t += 512) {
            int r = t >> 4, c = t & 15;
            uint32_t so = r * 256 + ((c ^ (r & 7)) << 4);
            cp16(sb + SA_BUF + so, ahi4 + (row0 + r) * 16 + c);
            cp16(sb + SA_BUF + 16384 + so, alo4 + (row0 + r) * 16 + c);
        }
    }
    CP_COMMIT();
    CP_WAIT0();
    __syncthreads();

    int w = tid >> 5, lane = tid & 31;
    int mBase = (w >> 2) * 16;           // 4 m-groups of 16 rows
    int nBase = (w & 3) * 32;            // 4 n-groups of 32 cols
    int arow = lane & 15;
    int asel = lane >> 4;
    int brow_in = (lane & 7) + ((lane >> 3) & 1) * 8;
    int bsel = lane >> 4;
    int r0 = lane >> 2;
    int c2 = (lane & 3) * 2;

    int buf = 0;
    for (int tb = tb0; tb < NTILES; tb += gridDim.x) {
        int tn = tb + gridDim.x;
        if (tn < NTILES) {
            uint32_t ab = sb + SA_BUF + (buf ^ 1) * ABUF_SZ;
            int rown = tn * 64;
            for (int t = tid; t < 1024; t += 512) {
                int r = t >> 4, c = t & 15;
                uint32_t so = r * 256 + ((c ^ (r & 7)) << 4);
                cp16(ab + so, ahi4 + (rown + r) * 16 + c);
                cp16(ab + 16384 + so, alo4 + (rown + r) * 16 + c);
            }
        }
        CP_COMMIT();

        uint32_t sa_hi = sb + SA_BUF + buf * ABUF_SZ;
        uint32_t sa_lo = sa_hi + 16384;

        float acc[4][4];
        #pragma unroll
        for (int nt = 0; nt < 4; nt++)
            #pragma unroll
            for (int j = 0; j < 4; j++) acc[nt][j] = 0.f;

        #pragma unroll
        for (int ks = 0; ks < 8; ks++) {
            uint32_t ah[4], al[4];
            int achunk = ks * 2 + asel;
            {
                int r = mBase + arow;
                uint32_t off = r * 256 + ((achunk ^ (r & 7)) << 4);
                ldsm_x4(ah, sa_hi + off);
                ldsm_x4(al, sa_lo + off);
            }
            uint32_t bh[2][4], bo[2][4];
            int brow = ks * 16 + brow_in;
            #pragma unroll
            for (int nt2 = 0; nt2 < 2; nt2++) {
                int chunk = ((nBase + nt2 * 16) >> 3) + bsel;
                uint32_t off = brow * 256 + ((chunk ^ (brow & 7)) << 4);
                ldsm_x4_t(bh[nt2], sb + SW_HI + off);
                ldsm_x4_t(bo[nt2], sb + SW_LO + off);
            }
            #pragma unroll
            for (int nt = 0; nt < 4; nt++) {
                const uint32_t* ph = &bh[nt >> 1][(nt & 1) * 2];
                const uint32_t* pl = &bo[nt >> 1][(nt & 1) * 2];
                mma16816(acc[nt], ah, ph);
                mma16816(acc[nt], al, ph);
                mma16816(acc[nt], ah, pl);
            }
        }

        int row0 = tb * 64;
        #pragma unroll
        for (int nt = 0; nt < 4; nt++) {
            int col = nBase + nt * 8 + c2;
            float2 bi = *(const float2*)(bias + col);
            int g0 = row0 + mBase + r0;
            float2 o0 = {acc[nt][0] + bi.x, acc[nt][1] + bi.y};
            *(float2*)(out + (size_t)g0 * DIM + col) = o0;
            float2 o1 = {acc[nt][2] + bi.x, acc[nt][3] + bi.y};
            *(float2*)(out + (size_t)(g0 + 8) * DIM + col) = o1;
        }

        CP_WAIT0();
        __syncthreads();
        buf ^= 1;
    }
}

// ---------------- GATv2 aggregation (R8-exact + ex2 fold) ----------------
__device__ __forceinline__ float leaky_dot(float4 v, float4 x, float4 w) {
    float zx = v.x + x.x, zy = v.y + x.y, zz = v.z + x.z, zw = v.w + x.w;
    zx = fmaxf(zx, NEG_SLOPE * zx);
    zy = fmaxf(zy, NEG_SLOPE * zy);
    zz = fmaxf(zz, NEG_SLOPE * zz);
    zw = fmaxf(zw, NEG_SLOPE * zw);
    return zx * w.x + zy * w.y + zz * w.z + zw * w.w;
}
__device__ __forceinline__ float hred8(float d) {
    d += __shfl_xor_sync(0xffffffffu, d, 1);
    d += __shfl_xor_sync(0xffffffffu, d, 2);
    d += __shfl_xor_sync(0xffffffffu, d, 4);
    return d;
}
__device__ __forceinline__ float ex2(float x) {
    float r;
    asm("ex2.approx.f32 %0, %1;" : "=f"(r) : "f"(x));
    return r;
}

__global__ __launch_bounds__(256) void k_gat(
    const float* __restrict__ xl, const float* __restrict__ xr,
    const float* __restrict__ att, const float* __restrict__ conv_bias,
    const float* __restrict__ bn_gamma, const float* __restrict__ bn_beta,
    const float* __restrict__ bn_mean, const float* __restrict__ bn_var,
    float* __restrict__ hout, int write_bf, int write_f32)
{
    int i = blockIdx.x * 8 + (threadIdx.x >> 5);
    if (i >= NODES) return;
    int lane = threadIdx.x & 31;
    int c = lane * 4;

    float4 w = *(const float4*)(att + c);
    w.x *= LOG2E; w.y *= LOG2E; w.z *= LOG2E; w.w *= LOG2E;   // fold log2e: exp(d)=2^(d')
    float4 xr4 = *(const float4*)(xr + (size_t)i * DIM + c);

    float4 xls = *(const float4*)(xl + (size_t)i * DIM + c);
    float m0 = hred8(leaky_dot(xls, xr4, w));
    float denom = 1.0f;
    float4 acc = xls;

    int beg = d_rowptr[i];
    int end = d_rowptr[i + 1];
    int j = beg;
    for (; j + 4 <= end; j += 4) {
        uint32_t s0 = d_srcs[j];
        uint32_t s1 = d_srcs[j + 1];
        uint32_t s2 = d_srcs[j + 2];
        uint32_t s3 = d_srcs[j + 3];
        float4 v0 = *(const float4*)(xl + (size_t)s0 * DIM + c);
        float4 v1 = *(const float4*)(xl + (size_t)s1 * DIM + c);
        float4 v2 = *(const float4*)(xl + (size_t)s2 * DIM + c);
        float4 v3 = *(const float4*)(xl + (size_t)s3 * DIM + c);
        float d0 = hred8(leaky_dot(v0, xr4, w));
        float d1 = hred8(leaky_dot(v1, xr4, w));
        float d2 = hred8(leaky_dot(v2, xr4, w));
        float d3 = hred8(leaky_dot(v3, xr4, w));
        float a0 = ex2(d0 - m0);
        float a1 = ex2(d1 - m0);
        float a2 = ex2(d2 - m0);
        float a3 = ex2(d3 - m0);
        denom += (a0 + a1) + (a2 + a3);
        acc.x += (a0 * v0.x + a1 * v1.x) + (a2 * v2.x + a3 * v3.x);
        acc.y += (a0 * v0.y + a1 * v1.y) + (a2 * v2.y + a3 * v3.y);
        acc.z += (a0 * v0.z + a1 * v1.z) + (a2 * v2.z + a3 * v3.z);
        acc.w += (a0 * v0.w + a1 * v1.w) + (a2 * v2.w + a3 * v3.w);
    }
    for (; j < end; j++) {
        uint32_t s0 = d_srcs[j];
        float4 v0 = *(const float4*)(xl + (size_t)s0 * DIM + c);
        float a0 = ex2(hred8(leaky_dot(v0, xr4, w)) - m0);
        denom += a0;
        acc.x += a0 * v0.x;
        acc.y += a0 * v0.y;
        acc.z += a0 * v0.z;
        acc.w += a0 * v0.w;
    }

    float inv = 1.0f / denom;
    float4 bias = *(const float4*)(conv_bias + c);
    float4 ga = *(const float4*)(bn_gamma + c);
    float4 be = *(const float4*)(bn_beta + c);
    float4 mu = *(const float4*)(bn_mean + c);
    float4 va = *(const float4*)(bn_var + c);
    float4 o;
    o.x = fmaxf((acc.x * inv + bias.x - mu.x) * rsqrtf(va.x + BN_EPS) * ga.x + be.x, 0.f);
    o.y = fmaxf((acc.y * inv + bias.y - mu.y) * rsqrtf(va.y + BN_EPS) * ga.y + be.y, 0.f);
    o.z = fmaxf((acc.z * inv + bias.z - mu.z) * rsqrtf(va.z + BN_EPS) * ga.z + be.z, 0.f);
    o.w = fmaxf((acc.w * inv + bias.w - mu.w) * rsqrtf(va.w + BN_EPS) * ga.w + be.w, 0.f);

    if (write_f32) *(float4*)(hout + (size_t)i * DIM + c) = o;
    if (write_bf) {
        __nv_bfloat16 hx = __float2bfloat16(o.x);
        __nv_bfloat16 hy = __float2bfloat16(o.y);
        __nv_bfloat16 hz = __float2bfloat16(o.z);
        __nv_bfloat16 hw = __float2bfloat16(o.w);
        __nv_bfloat162* ph = (__nv_bfloat162*)(d_hhi + (size_t)i * DIM + c);
        ph[0] = __nv_bfloat162(hx, hy);
        ph[1] = __nv_bfloat162(hz, hw);
        __nv_bfloat162* pl = (__nv_bfloat162*)(d_hlo + (size_t)i * DIM + c);
        pl[0] = __nv_bfloat162(__float2bfloat16(o.x - __bfloat162float(hx)),
                               __float2bfloat16(o.y - __bfloat162float(hy)));
        pl[1] = __nv_bfloat162(__float2bfloat16(o.z - __bfloat162float(hz)),
                               __float2bfloat16(o.w - __bfloat162float(hw)));
    }
}

// ---------------- mean pool (batch sorted) + MLP 128->64->2 ----------------
__global__ void k_pool_mlp(
    const float* __restrict__ h, const int* __restrict__ batch,
    const float* __restrict__ W1, const float* __restrict__ b1,
    const float* __restrict__ W2, const float* __restrict__ b2,
    float* __restrict__ out)
{
    __shared__ float p[DIM];
    __shared__ float hid[64];
    int g = blockIdx.x;
    int t = threadIdx.x;

    int lo = 0, hi = NODES;
    while (lo < hi) { int mid = (lo + hi) >> 1; if (batch[mid] < g) lo = mid + 1; else hi = mid; }
    int beg = lo;
    hi = NODES;
    while (lo < hi) { int mid = (lo + hi) >> 1; if (batch[mid] < g + 1) lo = mid + 1; else hi = mid; }
    int end = lo;

    float sum = 0.f;
    for (int n = beg; n < end; n++) sum += h[(size_t)n * DIM + t];
    float cnt = (float)(end - beg);
    p[t] = sum / fmaxf(cnt, 1.0f);
    __syncthreads();

    if (t < 64) {
        float a = b1[t];
        #pragma unroll 8
        for (int k = 0; k < DIM; k++) a = fmaf(p[k], W1[k * 64 + t], a);
        hid[t] = fmaxf(a, 0.f);
    }
    __syncthreads();

    if (t < 2) {
        float a = b2[t];
        #pragma unroll 8
        for (int k = 0; k < 64; k++) a = fmaf(hid[k], W2[k * 2 + t], a);
        out[g * 2 + t] = a;
    }
}

// ---------------- launch ----------------
extern "C" void kernel_launch(void* const* d_in, const int* in_sizes, int n_in,
                              void* d_out, int out_size)
{
    const float* x     = (const float*)d_in[0];
    const int*   ei    = (const int*)d_in[1];
    const int*   batch = (const int*)d_in[2];
    const float* Wl    = (const float*)d_in[3];
    const float* bl    = (const float*)d_in[4];
    const float* Wr    = (const float*)d_in[5];
    const float* br    = (const float*)d_in[6];
    const float* att   = (const float*)d_in[7];
    const float* cb    = (const float*)d_in[8];
    const float* bng   = (const float*)d_in[9];
    const float* bnb   = (const float*)d_in[10];
    const float* bnm   = (const float*)d_in[11];
    const float* bnv   = (const float*)d_in[12];
    const float* W1    = (const float*)d_in[13];
    const float* b1    = (const float*)d_in[14];
    const float* W2    = (const float*)d_in[15];
    const float* b2    = (const float*)d_in[16];
    float* out = (float*)d_out;

    float *h0, *xl, *xr;
    __nv_bfloat16 *hhi, *hlo, *whi, *wlo;
    cudaGetSymbolAddress((void**)&h0, d_h0);
    cudaGetSymbolAddress((void**)&xl, d_xl);
    cudaGetSymbolAddress((void**)&xr, d_xr);
    cudaGetSymbolAddress((void**)&hhi, d_hhi);
    cudaGetSymbolAddress((void**)&hlo, d_hlo);
    cudaGetSymbolAddress((void**)&whi, d_whi);
    cudaGetSymbolAddress((void**)&wlo, d_wlo);

    static int smem_set = 0;
    if (!smem_set) {
        cudaFuncSetAttribute(k_gemm_tc, cudaFuncAttributeMaxDynamicSharedMemorySize, GSMEM);
        smem_set = 1;
    }

    dim3 ggrid(74, 2);

    // order: launch index 3 (ncu capture slot) = k_gemm_tc layer 0
    k_convx_zero<<<(NODES * DIM + 255) / 256, 256>>>(x);             // 0
    k_hist_cw<<<HIST_BLOCKS + 6, 256>>>(ei, Wl, Wr);                 // 1
    k_scan<<<1, 1024>>>();                                           // 2
    k_gemm_tc<<<ggrid, 512, GSMEM>>>(hhi, hlo, whi, wlo, bl, br);    // 3  <-- profiled
    k_scatter<<<(EDGES + 255) / 256, 256>>>(ei);                     // 4

    for (int l = 0; l < 3; l++) {
        if (l > 0) {
            k_gemm_tc<<<ggrid, 512, GSMEM>>>(
                hhi, hlo,
                whi + (size_t)l * 2 * DIM * DIM, wlo + (size_t)l * 2 * DIM * DIM,
                bl + l * DIM, br + l * DIM);
        }
        k_gat<<<NODES / 8, 256>>>(xl, xr,
                                  att + l * DIM, cb + l * DIM,
                                  bng + l * DIM, bnb + l * DIM,
                                  bnm + l * DIM, bnv + l * DIM,
                                  h0, (l < 2) ? 1 : 0, (l == 2) ? 1 : 0);
    }

    k_pool_mlp<<<GRAPHS, 128>>>(h0, batch, W1, b1, W2, b2, out);
}

// round 14
// speedup vs baseline: 1.1141x; 1.0848x over previous
#include <cuda_runtime.h>
#include <cuda_bf16.h>
#include <cstdint>

#define NODES 40000
#define EDGES 640000
#define DIM 128
#define GRAPHS 512
#define NEG_SLOPE 0.2f
#define BN_EPS 1e-5f
#define LOG2E 1.4426950408889634f

// ---------------- scratch (no allocations allowed) ----------------
__device__ float d_h0[NODES * DIM];
__device__ float d_xl[NODES * DIM];
__device__ float d_xr[NODES * DIM];
__device__ __nv_bfloat16 d_hhi[NODES * DIM];
__device__ __nv_bfloat16 d_hlo[NODES * DIM];
__device__ __nv_bfloat16 d_whi[3 * 2 * DIM * DIM];
__device__ __nv_bfloat16 d_wlo[3 * 2 * DIM * DIM];
__device__ int d_deg[NODES];
__device__ int d_rowptr[NODES + 1];
__device__ int d_cursor[NODES];
__device__ int d_srcs[EDGES];

__device__ __forceinline__ uint32_t smem_u32(const void* p) {
    uint32_t a;
    asm("{ .reg .u64 t; cvta.to.shared.u64 t, %1; cvt.u32.u64 %0, t; }" : "=r"(a) : "l"(p));
    return a;
}
__device__ __forceinline__ void ldsm_x4(uint32_t* r, uint32_t addr) {
    asm volatile("ldmatrix.sync.aligned.m8n8.x4.shared.b16 {%0,%1,%2,%3}, [%4];"
                 : "=r"(r[0]), "=r"(r[1]), "=r"(r[2]), "=r"(r[3]) : "r"(addr));
}
__device__ __forceinline__ void ldsm_x4_t(uint32_t* r, uint32_t addr) {
    asm volatile("ldmatrix.sync.aligned.m8n8.x4.trans.shared.b16 {%0,%1,%2,%3}, [%4];"
                 : "=r"(r[0]), "=r"(r[1]), "=r"(r[2]), "=r"(r[3]) : "r"(addr));
}
__device__ __forceinline__ void mma16816(float* c, const uint32_t* a, const uint32_t* b) {
    asm volatile(
        "mma.sync.aligned.m16n8k16.row.col.f32.bf16.bf16.f32 "
        "{%0,%1,%2,%3}, {%4,%5,%6,%7}, {%8,%9}, {%0,%1,%2,%3};"
        : "+f"(c[0]), "+f"(c[1]), "+f"(c[2]), "+f"(c[3])
        : "r"(a[0]), "r"(a[1]), "r"(a[2]), "r"(a[3]), "r"(b[0]), "r"(b[1]));
}
__device__ __forceinline__ void cp16(uint32_t saddr, const void* gaddr) {
    asm volatile("cp.async.cg.shared.global [%0], [%1], 16;" :: "r"(saddr), "l"(gaddr));
}
#define CP_COMMIT() asm volatile("cp.async.commit_group;" ::: "memory")
#define CP_WAIT0()  asm volatile("cp.async.wait_group 0;" ::: "memory")

// ---------------- fused: convert x + zero deg + convert weights ----------------
#define CONVX_BLOCKS ((NODES * DIM) / 256)   // 20000
__global__ void k_conv_all(const float* __restrict__ x,
                           const float* __restrict__ Wl, const float* __restrict__ Wr) {
    if (blockIdx.x < CONVX_BLOCKS) {
        int i = blockIdx.x * blockDim.x + threadIdx.x;
        float v = x[i];
        __nv_bfloat16 h = __float2bfloat16(v);
        d_hhi[i] = h;
        d_hlo[i] = __float2bfloat16(v - __bfloat162float(h));
        if (i < NODES) d_deg[i] = 0;
    } else {
        int b = blockIdx.x - CONVX_BLOCKS;   // 0..5
        int l = b >> 1, m = b & 1;
        const float* W = (m ? Wr : Wl) + (size_t)l * DIM * DIM;
        __nv_bfloat16* oh = d_whi + (size_t)(l * 2 + m) * DIM * DIM;
        __nv_bfloat16* ol = d_wlo + (size_t)(l * 2 + m) * DIM * DIM;
        for (int t = threadIdx.x; t < DIM * DIM; t += blockDim.x) {
            float v = W[t];
            __nv_bfloat16 h = __float2bfloat16(v);
            oh[t] = h;
            ol[t] = __float2bfloat16(v - __bfloat162float(h));
        }
    }
}

__global__ void k_hist(const int* __restrict__ ei) {
    int e = blockIdx.x * blockDim.x + threadIdx.x;
    if (e < EDGES) atomicAdd(&d_deg[ei[EDGES + e]], 1);
}

#define SCAN_CH 40
__global__ void k_scan() {
    __shared__ int ws[32];
    int t = threadIdx.x, lane = t & 31, wid = t >> 5;
    int base = t * SCAN_CH;
    int s = 0;
    #pragma unroll 4
    for (int k = 0; k < SCAN_CH; k++) {
        int idx = base + k;
        if (idx < NODES) s += d_deg[idx];
    }
    int x = s;
    #pragma unroll
    for (int o = 1; o < 32; o <<= 1) {
        int y = __shfl_up_sync(0xffffffffu, x, o);
        if (lane >= o) x += y;
    }
    if (lane == 31) ws[wid] = x;
    __syncthreads();
    if (wid == 0) {
        int sv = ws[lane], sx = sv;
        #pragma unroll
        for (int o = 1; o < 32; o <<= 1) {
            int y = __shfl_up_sync(0xffffffffu, sx, o);
            if (lane >= o) sx += y;
        }
        ws[lane] = sx - sv;
    }
    __syncthreads();
    int run = ws[wid] + x - s;
    #pragma unroll 4
    for (int k = 0; k < SCAN_CH; k++) {
        int idx = base + k;
        if (idx < NODES) {
            int dg = d_deg[idx];
            d_rowptr[idx] = run;
            d_cursor[idx] = run;
            run += dg;
        }
    }
    if (t == 1023) d_rowptr[NODES] = run;
}
__global__ void k_scatter(const int* __restrict__ ei) {
    int e = blockIdx.x * blockDim.x + threadIdx.x;
    if (e < EDGES) {
        int dst = ei[EDGES + e];
        int pos = atomicAdd(&d_cursor[dst], 1);
        d_srcs[pos] = ei[e];
    }
}

// ---------------- persistent HMMA dual GEMM (R8 best version) ----------------
#define SW_HI 0
#define SW_LO 32768
#define SA_BUF 65536
#define ABUF_SZ 32768
#define GSMEM 131072
#define NTILES (NODES / 64)

__global__ __launch_bounds__(256, 1) void k_gemm_tc(
    const __nv_bfloat16* __restrict__ Ahi, const __nv_bfloat16* __restrict__ Alo,
    const __nv_bfloat16* __restrict__ Whi, const __nv_bfloat16* __restrict__ Wlo,
    const float* __restrict__ bl, const float* __restrict__ br)
{
    extern __shared__ char smem[];
    uint32_t sb = smem_u32(smem);
    int tid = threadIdx.x;
    int mat = blockIdx.y;

    const float* bias = mat ? br : bl;
    float* out = mat ? d_xr : d_xl;
    const uint4* ahi4 = (const uint4*)Ahi;
    const uint4* alo4 = (const uint4*)Alo;
    const uint4* wh4 = (const uint4*)(Whi + (size_t)mat * DIM * DIM);
    const uint4* wl4 = (const uint4*)(Wlo + (size_t)mat * DIM * DIM);

    int tb0 = blockIdx.x;
    for (int t = tid; t < 2048; t += 256) {
        int r = t >> 4, c = t & 15;
        uint32_t so = r * 256 + ((c ^ (r & 7)) << 4);
        cp16(sb + SW_HI + so, wh4 + t);
        cp16(sb + SW_LO + so, wl4 + t);
    }
    if (tb0 < NTILES) {
        int row0 = tb0 * 64;
        for (int t = tid; t < 1024; t += 256) {
            int r = t >> 4, c = t & 15;
            uint32_t so = r * 256 + ((c ^ (r & 7)) << 4);
            cp16(sb + SA_BUF + so, ahi4 + (row0 + r) * 16 + c);
            cp16(sb + SA_BUF + 16384 + so, alo4 + (row0 + r) * 16 + c);
        }
    }
    CP_COMMIT();
    CP_WAIT0();
    __syncthreads();

    int w = tid >> 5, lane = tid & 31;
    int mBase = (w >> 2) * 32;
    int nBase = (w & 3) * 32;
    int arow = lane & 15;
    int asel = lane >> 4;
    int brow_in = (lane & 7) + ((lane >> 3) & 1) * 8;
    int bsel = lane >> 4;
    int r0 = lane >> 2;
    int c2 = (lane & 3) * 2;

    int buf = 0;
    for (int tb = tb0; tb < NTILES; tb += gridDim.x) {
        int tn = tb + gridDim.x;
        if (tn < NTILES) {
            uint32_t ab = sb + SA_BUF + (buf ^ 1) * ABUF_SZ;
            int rown = tn * 64;
            for (int t = tid; t < 1024; t += 256) {
                int r = t >> 4, c = t & 15;
                uint32_t so = r * 256 + ((c ^ (r & 7)) << 4);
                cp16(ab + so, ahi4 + (rown + r) * 16 + c);
                cp16(ab + 16384 + so, alo4 + (rown + r) * 16 + c);
            }
        }
        CP_COMMIT();

        uint32_t sa_hi = sb + SA_BUF + buf * ABUF_SZ;
        uint32_t sa_lo = sa_hi + 16384;

        float acc[2][4][4];
        #pragma unroll
        for (int mt = 0; mt < 2; mt++)
            #pragma unroll
            for (int nt = 0; nt < 4; nt++)
                #pragma unroll
                for (int j = 0; j < 4; j++) acc[mt][nt][j] = 0.f;

        #pragma unroll
        for (int ks = 0; ks < 8; ks++) {
            uint32_t ah[2][4], al[2][4];
            int achunk = ks * 2 + asel;
            #pragma unroll
            for (int mt = 0; mt < 2; mt++) {
                int r = mBase + mt * 16 + arow;
                uint32_t off = r * 256 + ((achunk ^ (r & 7)) << 4);
                ldsm_x4(ah[mt], sa_hi + off);
                ldsm_x4(al[mt], sa_lo + off);
            }
            uint32_t bh[2][4], bo[2][4];
            int brow = ks * 16 + brow_in;
            #pragma unroll
            for (int nt2 = 0; nt2 < 2; nt2++) {
                int chunk = ((nBase + nt2 * 16) >> 3) + bsel;
                uint32_t off = brow * 256 + ((chunk ^ (brow & 7)) << 4);
                ldsm_x4_t(bh[nt2], sb + SW_HI + off);
                ldsm_x4_t(bo[nt2], sb + SW_LO + off);
            }
            #pragma unroll
            for (int mt = 0; mt < 2; mt++)
                #pragma unroll
                for (int nt = 0; nt < 4; nt++) {
                    const uint32_t* ph = &bh[nt >> 1][(nt & 1) * 2];
                    const uint32_t* pl = &bo[nt >> 1][(nt & 1) * 2];
                    mma16816(acc[mt][nt], ah[mt], ph);
                    mma16816(acc[mt][nt], al[mt], ph);
                    mma16816(acc[mt][nt], ah[mt], pl);
                }
        }

        int row0 = tb * 64;
        #pragma unroll
        for (int nt = 0; nt < 4; nt++) {
            int col = nBase + nt * 8 + c2;
            float2 bi = *(const float2*)(bias + col);
            #pragma unroll
            for (int mt = 0; mt < 2; mt++) {
                int g0 = row0 + mBase + mt * 16 + r0;
                float2 o0 = {acc[mt][nt][0] + bi.x, acc[mt][nt][1] + bi.y};
                *(float2*)(out + (size_t)g0 * DIM + col) = o0;
                float2 o1 = {acc[mt][nt][2] + bi.x, acc[mt][nt][3] + bi.y};
                *(float2*)(out + (size_t)(g0 + 8) * DIM + col) = o1;
            }
        }

        CP_WAIT0();
        __syncthreads();
        buf ^= 1;
    }
}

// ---------------- GATv2 aggregation (ex2 variant) ----------------
__device__ __forceinline__ float leaky_dot(float4 v, float4 x, float4 w) {
    float zx = v.x + x.x, zy = v.y + x.y, zz = v.z + x.z, zw = v.w + x.w;
    zx = fmaxf(zx, NEG_SLOPE * zx);
    zy = fmaxf(zy, NEG_SLOPE * zy);
    zz = fmaxf(zz, NEG_SLOPE * zz);
    zw = fmaxf(zw, NEG_SLOPE * zw);
    return zx * w.x + zy * w.y + zz * w.z + zw * w.w;
}
__device__ __forceinline__ float hred8(float d) {
    d += __shfl_xor_sync(0xffffffffu, d, 1);
    d += __shfl_xor_sync(0xffffffffu, d, 2);
    d += __shfl_xor_sync(0xffffffffu, d, 4);
    return d;
}
__device__ __forceinline__ float ex2(float x) {
    float r;
    asm("ex2.approx.f32 %0, %1;" : "=f"(r) : "f"(x));
    return r;
}

__global__ __launch_bounds__(256) void k_gat(
    const float* __restrict__ xl, const float* __restrict__ xr,
    const float* __restrict__ att, const float* __restrict__ conv_bias,
    const float* __restrict__ bn_gamma, const float* __restrict__ bn_beta,
    const float* __restrict__ bn_mean, const float* __restrict__ bn_var,
    float* __restrict__ hout, int write_bf, int write_f32)
{
    int i = blockIdx.x * 8 + (threadIdx.x >> 5);
    if (i >= NODES) return;
    int lane = threadIdx.x & 31;
    int c = lane * 4;

    float4 w = *(const float4*)(att + c);
    w.x *= LOG2E; w.y *= LOG2E; w.z *= LOG2E; w.w *= LOG2E;
    float4 xr4 = *(const float4*)(xr + (size_t)i * DIM + c);

    float4 xls = *(const float4*)(xl + (size_t)i * DIM + c);
    float m0 = hred8(leaky_dot(xls, xr4, w));
    float denom = 1.0f;
    float4 acc = xls;

    int beg = d_rowptr[i];
    int end = d_rowptr[i + 1];
    int j = beg;
    for (; j + 4 <= end; j += 4) {
        uint32_t s0 = d_srcs[j];
        uint32_t s1 = d_srcs[j + 1];
        uint32_t s2 = d_srcs[j + 2];
        uint32_t s3 = d_srcs[j + 3];
        float4 v0 = *(const float4*)(xl + (size_t)s0 * DIM + c);
        float4 v1 = *(const float4*)(xl + (size_t)s1 * DIM + c);
        float4 v2 = *(const float4*)(xl + (size_t)s2 * DIM + c);
        float4 v3 = *(const float4*)(xl + (size_t)s3 * DIM + c);
        float d0 = hred8(leaky_dot(v0, xr4, w));
        float d1 = hred8(leaky_dot(v1, xr4, w));
        float d2 = hred8(leaky_dot(v2, xr4, w));
        float d3 = hred8(leaky_dot(v3, xr4, w));
        float a0 = ex2(d0 - m0);
        float a1 = ex2(d1 - m0);
        float a2 = ex2(d2 - m0);
        float a3 = ex2(d3 - m0);
        denom += (a0 + a1) + (a2 + a3);
        acc.x += (a0 * v0.x + a1 * v1.x) + (a2 * v2.x + a3 * v3.x);
        acc.y += (a0 * v0.y + a1 * v1.y) + (a2 * v2.y + a3 * v3.y);
        acc.z += (a0 * v0.z + a1 * v1.z) + (a2 * v2.z + a3 * v3.z);
        acc.w += (a0 * v0.w + a1 * v1.w) + (a2 * v2.w + a3 * v3.w);
    }
    for (; j < end; j++) {
        uint32_t s0 = d_srcs[j];
        float4 v0 = *(const float4*)(xl + (size_t)s0 * DIM + c);
        float a0 = ex2(hred8(leaky_dot(v0, xr4, w)) - m0);
        denom += a0;
        acc.x += a0 * v0.x;
        acc.y += a0 * v0.y;
        acc.z += a0 * v0.z;
        acc.w += a0 * v0.w;
    }

    float inv = 1.0f / denom;
    float4 bias = *(const float4*)(conv_bias + c);
    float4 ga = *(const float4*)(bn_gamma + c);
    float4 be = *(const float4*)(bn_beta + c);
    float4 mu = *(const float4*)(bn_mean + c);
    float4 va = *(const float4*)(bn_var + c);
    float4 o;
    o.x = fmaxf((acc.x * inv + bias.x - mu.x) * rsqrtf(va.x + BN_EPS) * ga.x + be.x, 0.f);
    o.y = fmaxf((acc.y * inv + bias.y - mu.y) * rsqrtf(va.y + BN_EPS) * ga.y + be.y, 0.f);
    o.z = fmaxf((acc.z * inv + bias.z - mu.z) * rsqrtf(va.z + BN_EPS) * ga.z + be.z, 0.f);
    o.w = fmaxf((acc.w * inv + bias.w - mu.w) * rsqrtf(va.w + BN_EPS) * ga.w + be.w, 0.f);

    if (write_f32) *(float4*)(hout + (size_t)i * DIM + c) = o;
    if (write_bf) {
        __nv_bfloat16 hx = __float2bfloat16(o.x);
        __nv_bfloat16 hy = __float2bfloat16(o.y);
        __nv_bfloat16 hz = __float2bfloat16(o.z);
        __nv_bfloat16 hw = __float2bfloat16(o.w);
        __nv_bfloat162* ph = (__nv_bfloat162*)(d_hhi + (size_t)i * DIM + c);
        ph[0] = __nv_bfloat162(hx, hy);
        ph[1] = __nv_bfloat162(hz, hw);
        __nv_bfloat162* pl = (__nv_bfloat162*)(d_hlo + (size_t)i * DIM + c);
        pl[0] = __nv_bfloat162(__float2bfloat16(o.x - __bfloat162float(hx)),
                               __float2bfloat16(o.y - __bfloat162float(hy)));
        pl[1] = __nv_bfloat162(__float2bfloat16(o.z - __bfloat162float(hz)),
                               __float2bfloat16(o.w - __bfloat162float(hw)));
    }
}

// ---------------- mean pool (batch sorted) + MLP 128->64->2 ----------------
__global__ void k_pool_mlp(
    const float* __restrict__ h, const int* __restrict__ batch,
    const float* __restrict__ W1, const float* __restrict__ b1,
    const float* __restrict__ W2, const float* __restrict__ b2,
    float* __restrict__ out)
{
    __shared__ float p[DIM];
    __shared__ float hid[64];
    int g = blockIdx.x;
    int t = threadIdx.x;

    int lo = 0, hi = NODES;
    while (lo < hi) { int mid = (lo + hi) >> 1; if (batch[mid] < g) lo = mid + 1; else hi = mid; }
    int beg = lo;
    hi = NODES;
    while (lo < hi) { int mid = (lo + hi) >> 1; if (batch[mid] < g + 1) lo = mid + 1; else hi = mid; }
    int end = lo;

    float sum = 0.f;
    for (int n = beg; n < end; n++) sum += h[(size_t)n * DIM + t];
    float cnt = (float)(end - beg);
    p[t] = sum / fmaxf(cnt, 1.0f);
    __syncthreads();

    if (t < 64) {
        float a = b1[t];
        #pragma unroll 8
        for (int k = 0; k < DIM; k++) a = fmaf(p[k], W1[k * 64 + t], a);
        hid[t] = fmaxf(a, 0.f);
    }
    __syncthreads();

    if (t < 2) {
        float a = b2[t];
        #pragma unroll 8
        for (int k = 0; k < 64; k++) a = fmaf(hid[k], W2[k * 2 + t], a);
        out[g * 2 + t] = a;
    }
}

// ---------------- launch ----------------
extern "C" void kernel_launch(void* const* d_in, const int* in_sizes, int n_in,
                              void* d_out, int out_size)
{
    const float* x     = (const float*)d_in[0];
    const int*   ei    = (const int*)d_in[1];
    const int*   batch = (const int*)d_in[2];
    const float* Wl    = (const float*)d_in[3];
    const float* bl    = (const float*)d_in[4];
    const float* Wr    = (const float*)d_in[5];
    const float* br    = (const float*)d_in[6];
    const float* att   = (const float*)d_in[7];
    const float* cb    = (const float*)d_in[8];
    const float* bng   = (const float*)d_in[9];
    const float* bnb   = (const float*)d_in[10];
    const float* bnm   = (const float*)d_in[11];
    const float* bnv   = (const float*)d_in[12];
    const float* W1    = (const float*)d_in[13];
    const float* b1    = (const float*)d_in[14];
    const float* W2    = (const float*)d_in[15];
    const float* b2    = (const float*)d_in[16];
    float* out = (float*)d_out;

    float *h0, *xl, *xr;
    __nv_bfloat16 *hhi, *hlo, *whi, *wlo;
    cudaGetSymbolAddress((void**)&h0, d_h0);
    cudaGetSymbolAddress((void**)&xl, d_xl);
    cudaGetSymbolAddress((void**)&xr, d_xr);
    cudaGetSymbolAddress((void**)&hhi, d_hhi);
    cudaGetSymbolAddress((void**)&hlo, d_hlo);
    cudaGetSymbolAddress((void**)&whi, d_whi);
    cudaGetSymbolAddress((void**)&wlo, d_wlo);

    static int init_done = 0;
    static cudaStream_t s2;
    static cudaEvent_t evA, evB;
    if (!init_done) {
        cudaFuncSetAttribute(k_gemm_tc, cudaFuncAttributeMaxDynamicSharedMemorySize, GSMEM);
        cudaStreamCreateWithFlags(&s2, cudaStreamNonBlocking);
        cudaEventCreateWithFlags(&evA, cudaEventDisableTiming);
        cudaEventCreateWithFlags(&evB, cudaEventDisableTiming);
        init_done = 1;
    }

    dim3 ggrid(74, 2);

    // main stream (0): conv_all -> gemm L0 -> [join] -> gat/gemm chain -> pool
    // side stream s2:  [fork after conv_all] hist -> scan -> scatter
    k_conv_all<<<CONVX_BLOCKS + 6, 256>>>(x, Wl, Wr);                 // #0
    cudaEventRecord(evA, 0);
    cudaStreamWaitEvent(s2, evA, 0);
    k_hist<<<(EDGES + 255) / 256, 256, 0, s2>>>(ei);                  // #1
    k_scan<<<1, 1024, 0, s2>>>();                                     // #2
    k_gemm_tc<<<ggrid, 256, GSMEM>>>(hhi, hlo, whi, wlo, bl, br);     // #3  <-- profiled (overlaps CSR)
    k_scatter<<<(EDGES + 255) / 256, 256, 0, s2>>>(ei);               // #4
    cudaEventRecord(evB, s2);
    cudaStreamWaitEvent(0, evB, 0);

    for (int l = 0; l < 3; l++) {
        if (l > 0) {
            k_gemm_tc<<<ggrid, 256, GSMEM>>>(
                hhi, hlo,
                whi + (size_t)l * 2 * DIM * DIM, wlo + (size_t)l * 2 * DIM * DIM,
                bl + l * DIM, br + l * DIM);
        }
        k_gat<<<NODES / 8, 256>>>(xl, xr,
                                  att + l * DIM, cb + l * DIM,
                                  bng + l * DIM, bnb + l * DIM,
                                  bnm + l * DIM, bnv + l * DIM,
                                  h0, (l < 2) ? 1 : 0, (l == 2) ? 1 : 0);
    }

    k_pool_mlp<<<GRAPHS, 128>>>(h0, batch, W1, b1, W2, b2, out);
}

// round 15
// speedup vs baseline: 1.1894x; 1.0676x over previous
#include <cuda_runtime.h>
#include <cuda_bf16.h>
#include <cstdint>

#define NODES 40000
#define EDGES 640000
#define DIM 128
#define GRAPHS 512
#define NEG_SLOPE 0.2f
#define BN_EPS 1e-5f
#define LOG2E 1.4426950408889634f

// ---------------- scratch (no allocations allowed) ----------------
__device__ float d_h0[NODES * DIM];
__device__ float d_xl[NODES * DIM];
__device__ float d_xr[NODES * DIM];
__device__ __nv_bfloat16 d_hhi[NODES * DIM];
__device__ __nv_bfloat16 d_hlo[NODES * DIM];
__device__ __nv_bfloat16 d_whi[3 * 2 * DIM * DIM];
__device__ __nv_bfloat16 d_wlo[3 * 2 * DIM * DIM];
__device__ int d_deg[NODES];
__device__ int d_rowptr[NODES + 1];
__device__ int d_cursor[NODES];
__device__ int d_srcs[EDGES];

__device__ __forceinline__ uint32_t smem_u32(const void* p) {
    uint32_t a;
    asm("{ .reg .u64 t; cvta.to.shared.u64 t, %1; cvt.u32.u64 %0, t; }" : "=r"(a) : "l"(p));
    return a;
}
__device__ __forceinline__ void ldsm_x4(uint32_t* r, uint32_t addr) {
    asm volatile("ldmatrix.sync.aligned.m8n8.x4.shared.b16 {%0,%1,%2,%3}, [%4];"
                 : "=r"(r[0]), "=r"(r[1]), "=r"(r[2]), "=r"(r[3]) : "r"(addr));
}
__device__ __forceinline__ void ldsm_x4_t(uint32_t* r, uint32_t addr) {
    asm volatile("ldmatrix.sync.aligned.m8n8.x4.trans.shared.b16 {%0,%1,%2,%3}, [%4];"
                 : "=r"(r[0]), "=r"(r[1]), "=r"(r[2]), "=r"(r[3]) : "r"(addr));
}
__device__ __forceinline__ void mma16816(float* c, const uint32_t* a, const uint32_t* b) {
    asm volatile(
        "mma.sync.aligned.m16n8k16.row.col.f32.bf16.bf16.f32 "
        "{%0,%1,%2,%3}, {%4,%5,%6,%7}, {%8,%9}, {%0,%1,%2,%3};"
        : "+f"(c[0]), "+f"(c[1]), "+f"(c[2]), "+f"(c[3])
        : "r"(a[0]), "r"(a[1]), "r"(a[2]), "r"(a[3]), "r"(b[0]), "r"(b[1]));
}
__device__ __forceinline__ void cp16(uint32_t saddr, const void* gaddr) {
    asm volatile("cp.async.cg.shared.global [%0], [%1], 16;" :: "r"(saddr), "l"(gaddr));
}
#define CP_COMMIT() asm volatile("cp.async.commit_group;" ::: "memory")
#define CP_WAIT0()  asm volatile("cp.async.wait_group 0;" ::: "memory")

// ---------------- small kernels ----------------
__global__ void k_zero() {
    int i = blockIdx.x * blockDim.x + threadIdx.x;
    if (i < NODES) d_deg[i] = 0;
}
__global__ void k_conv_w(const float* __restrict__ Wl, const float* __restrict__ Wr) {
    int b = blockIdx.x;   // 0..5
    int l = b >> 1, m = b & 1;
    const float* W = (m ? Wr : Wl) + (size_t)l * DIM * DIM;
    __nv_bfloat16* oh = d_whi + (size_t)(l * 2 + m) * DIM * DIM;
    __nv_bfloat16* ol = d_wlo + (size_t)(l * 2 + m) * DIM * DIM;
    for (int t = threadIdx.x; t < DIM * DIM; t += blockDim.x) {
        float v = W[t];
        __nv_bfloat16 h = __float2bfloat16(v);
        oh[t] = h;
        ol[t] = __float2bfloat16(v - __bfloat162float(h));
    }
}
__global__ void k_hist(const int* __restrict__ ei) {
    int e = blockIdx.x * blockDim.x + threadIdx.x;
    if (e < EDGES) atomicAdd(&d_deg[ei[EDGES + e]], 1);
}
#define SCAN_CH 40
__global__ void k_scan() {
    __shared__ int ws[32];
    int t = threadIdx.x, lane = t & 31, wid = t >> 5;
    int base = t * SCAN_CH;
    int s = 0;
    #pragma unroll 4
    for (int k = 0; k < SCAN_CH; k++) {
        int idx = base + k;
        if (idx < NODES) s += d_deg[idx];
    }
    int x = s;
    #pragma unroll
    for (int o = 1; o < 32; o <<= 1) {
        int y = __shfl_up_sync(0xffffffffu, x, o);
        if (lane >= o) x += y;
    }
    if (lane == 31) ws[wid] = x;
    __syncthreads();
    if (wid == 0) {
        int sv = ws[lane], sx = sv;
        #pragma unroll
        for (int o = 1; o < 32; o <<= 1) {
            int y = __shfl_up_sync(0xffffffffu, sx, o);
            if (lane >= o) sx += y;
        }
        ws[lane] = sx - sv;
    }
    __syncthreads();
    int run = ws[wid] + x - s;
    #pragma unroll 4
    for (int k = 0; k < SCAN_CH; k++) {
        int idx = base + k;
        if (idx < NODES) {
            int dg = d_deg[idx];
            d_rowptr[idx] = run;
            d_cursor[idx] = run;
            run += dg;
        }
    }
    if (t == 1023) d_rowptr[NODES] = run;
}
__global__ void k_scatter(const int* __restrict__ ei) {
    int e = blockIdx.x * blockDim.x + threadIdx.x;
    if (e < EDGES) {
        int dst = ei[EDGES + e];
        int pos = atomicAdd(&d_cursor[dst], 1);
        d_srcs[pos] = ei[e];
    }
}

// ---------------- persistent HMMA dual GEMM (bf16 inputs; layers 1-2) ----------------
#define SW_HI 0
#define SW_LO 32768
#define SA_BUF 65536
#define ABUF_SZ 32768
#define GSMEM 131072
#define NTILES (NODES / 64)

__global__ __launch_bounds__(256, 1) void k_gemm_tc(
    const __nv_bfloat16* __restrict__ Ahi, const __nv_bfloat16* __restrict__ Alo,
    const __nv_bfloat16* __restrict__ Whi, const __nv_bfloat16* __restrict__ Wlo,
    const float* __restrict__ bl, const float* __restrict__ br)
{
    extern __shared__ char smem[];
    uint32_t sb = smem_u32(smem);
    int tid = threadIdx.x;
    int mat = blockIdx.y;

    const float* bias = mat ? br : bl;
    float* out = mat ? d_xr : d_xl;
    const uint4* ahi4 = (const uint4*)Ahi;
    const uint4* alo4 = (const uint4*)Alo;
    const uint4* wh4 = (const uint4*)(Whi + (size_t)mat * DIM * DIM);
    const uint4* wl4 = (const uint4*)(Wlo + (size_t)mat * DIM * DIM);

    int tb0 = blockIdx.x;
    for (int t = tid; t < 2048; t += 256) {
        int r = t >> 4, c = t & 15;
        uint32_t so = r * 256 + ((c ^ (r & 7)) << 4);
        cp16(sb + SW_HI + so, wh4 + t);
        cp16(sb + SW_LO + so, wl4 + t);
    }
    if (tb0 < NTILES) {
        int row0 = tb0 * 64;
        for (int t = tid; t < 1024; t += 256) {
            int r = t >> 4, c = t & 15;
            uint32_t so = r * 256 + ((c ^ (r & 7)) << 4);
            cp16(sb + SA_BUF + so, ahi4 + (row0 + r) * 16 + c);
            cp16(sb + SA_BUF + 16384 + so, alo4 + (row0 + r) * 16 + c);
        }
    }
    CP_COMMIT();
    CP_WAIT0();
    __syncthreads();

    int w = tid >> 5, lane = tid & 31;
    int mBase = (w >> 2) * 32;
    int nBase = (w & 3) * 32;
    int arow = lane & 15;
    int asel = lane >> 4;
    int brow_in = (lane & 7) + ((lane >> 3) & 1) * 8;
    int bsel = lane >> 4;
    int r0 = lane >> 2;
    int c2 = (lane & 3) * 2;

    int buf = 0;
    for (int tb = tb0; tb < NTILES; tb += gridDim.x) {
        int tn = tb + gridDim.x;
        if (tn < NTILES) {
            uint32_t ab = sb + SA_BUF + (buf ^ 1) * ABUF_SZ;
            int rown = tn * 64;
            for (int t = tid; t < 1024; t += 256) {
                int r = t >> 4, c = t & 15;
                uint32_t so = r * 256 + ((c ^ (r & 7)) << 4);
                cp16(ab + so, ahi4 + (rown + r) * 16 + c);
                cp16(ab + 16384 + so, alo4 + (rown + r) * 16 + c);
            }
        }
        CP_COMMIT();

        uint32_t sa_hi = sb + SA_BUF + buf * ABUF_SZ;
        uint32_t sa_lo = sa_hi + 16384;

        float acc[2][4][4];
        #pragma unroll
        for (int mt = 0; mt < 2; mt++)
            #pragma unroll
            for (int nt = 0; nt < 4; nt++)
                #pragma unroll
                for (int j = 0; j < 4; j++) acc[mt][nt][j] = 0.f;

        #pragma unroll
        for (int ks = 0; ks < 8; ks++) {
            uint32_t ah[2][4], al[2][4];
            int achunk = ks * 2 + asel;
            #pragma unroll
            for (int mt = 0; mt < 2; mt++) {
                int r = mBase + mt * 16 + arow;
                uint32_t off = r * 256 + ((achunk ^ (r & 7)) << 4);
                ldsm_x4(ah[mt], sa_hi + off);
                ldsm_x4(al[mt], sa_lo + off);
            }
            uint32_t bh[2][4], bo[2][4];
            int brow = ks * 16 + brow_in;
            #pragma unroll
            for (int nt2 = 0; nt2 < 2; nt2++) {
                int chunk = ((nBase + nt2 * 16) >> 3) + bsel;
                uint32_t off = brow * 256 + ((chunk ^ (brow & 7)) << 4);
                ldsm_x4_t(bh[nt2], sb + SW_HI + off);
                ldsm_x4_t(bo[nt2], sb + SW_LO + off);
            }
            #pragma unroll
            for (int mt = 0; mt < 2; mt++)
                #pragma unroll
                for (int nt = 0; nt < 4; nt++) {
                    const uint32_t* ph = &bh[nt >> 1][(nt & 1) * 2];
                    const uint32_t* pl = &bo[nt >> 1][(nt & 1) * 2];
                    mma16816(acc[mt][nt], ah[mt], ph);
                    mma16816(acc[mt][nt], al[mt], ph);
                    mma16816(acc[mt][nt], ah[mt], pl);
                }
        }

        int row0 = tb * 64;
        #pragma unroll
        for (int nt = 0; nt < 4; nt++) {
            int col = nBase + nt * 8 + c2;
            float2 bi = *(const float2*)(bias + col);
            #pragma unroll
            for (int mt = 0; mt < 2; mt++) {
                int g0 = row0 + mBase + mt * 16 + r0;
                float2 o0 = {acc[mt][nt][0] + bi.x, acc[mt][nt][1] + bi.y};
                *(float2*)(out + (size_t)g0 * DIM + col) = o0;
                float2 o1 = {acc[mt][nt][2] + bi.x, acc[mt][nt][3] + bi.y};
                *(float2*)(out + (size_t)(g0 + 8) * DIM + col) = o1;
            }
        }

        CP_WAIT0();
        __syncthreads();
        buf ^= 1;
    }
}

// ---------------- layer-0 GEMM: reads fp32 x, converts hi/lo inline ----------------
#define L0_SA_HI 65536
#define L0_SA_LO 81920
#define GSMEM_L0 98304

__global__ __launch_bounds__(256, 1) void k_gemm_l0(
    const float* __restrict__ X,
    const __nv_bfloat16* __restrict__ Whi, const __nv_bfloat16* __restrict__ Wlo,
    const float* __restrict__ bl, const float* __restrict__ br)
{
    extern __shared__ char smem[];
    uint32_t sb = smem_u32(smem);
    int tid = threadIdx.x;
    int mat = blockIdx.y;

    const float* bias = mat ? br : bl;
    float* out = mat ? d_xr : d_xl;
    const uint4* wh4 = (const uint4*)(Whi + (size_t)mat * DIM * DIM);
    const uint4* wl4 = (const uint4*)(Wlo + (size_t)mat * DIM * DIM);

    for (int t = tid; t < 2048; t += 256) {
        int r = t >> 4, c = t & 15;
        uint32_t so = r * 256 + ((c ^ (r & 7)) << 4);
        cp16(sb + SW_HI + so, wh4 + t);
        cp16(sb + SW_LO + so, wl4 + t);
    }
    CP_COMMIT();
    CP_WAIT0();
    __syncthreads();

    int w = tid >> 5, lane = tid & 31;
    int mBase = (w >> 2) * 32;
    int nBase = (w & 3) * 32;
    int arow = lane & 15;
    int asel = lane >> 4;
    int brow_in = (lane & 7) + ((lane >> 3) & 1) * 8;
    int bsel = lane >> 4;
    int r0 = lane >> 2;
    int c2 = (lane & 3) * 2;

    for (int tb = blockIdx.x; tb < NTILES; tb += gridDim.x) {
        int row0 = tb * 64;
        // load fp32 A tile, convert to bf16 hi/lo into swizzled smem
        for (int t = tid; t < 1024; t += 256) {
            int r = t >> 4, c = t & 15;          // c = 16B bf16 chunk = 8 floats
            const float4* xs = (const float4*)(X + (size_t)(row0 + r) * DIM + c * 8);
            float4 f0 = xs[0], f1 = xs[1];
            __nv_bfloat16 h0 = __float2bfloat16(f0.x), h1 = __float2bfloat16(f0.y);
            __nv_bfloat16 h2 = __float2bfloat16(f0.z), h3 = __float2bfloat16(f0.w);
            __nv_bfloat16 h4 = __float2bfloat16(f1.x), h5 = __float2bfloat16(f1.y);
            __nv_bfloat16 h6 = __float2bfloat16(f1.z), h7 = __float2bfloat16(f1.w);
            __nv_bfloat162 hi[4] = {
                __nv_bfloat162(h0, h1), __nv_bfloat162(h2, h3),
                __nv_bfloat162(h4, h5), __nv_bfloat162(h6, h7)};
            __nv_bfloat162 lo[4] = {
                __nv_bfloat162(__float2bfloat16(f0.x - __bfloat162float(h0)),
                               __float2bfloat16(f0.y - __bfloat162float(h1))),
                __nv_bfloat162(__float2bfloat16(f0.z - __bfloat162float(h2)),
                               __float2bfloat16(f0.w - __bfloat162float(h3))),
                __nv_bfloat162(__float2bfloat16(f1.x - __bfloat162float(h4)),
                               __float2bfloat16(f1.y - __bfloat162float(h5))),
                __nv_bfloat162(__float2bfloat16(f1.z - __bfloat162float(h6)),
                               __float2bfloat16(f1.w - __bfloat162float(h7)))};
            uint32_t so = r * 256 + ((c ^ (r & 7)) << 4);
            *(uint4*)(smem + L0_SA_HI + so) = *(uint4*)hi;
            *(uint4*)(smem + L0_SA_LO + so) = *(uint4*)lo;
        }
        __syncthreads();

        float acc[2][4][4];
        #pragma unroll
        for (int mt = 0; mt < 2; mt++)
            #pragma unroll
            for (int nt = 0; nt < 4; nt++)
                #pragma unroll
                for (int j = 0; j < 4; j++) acc[mt][nt][j] = 0.f;

        #pragma unroll
        for (int ks = 0; ks < 8; ks++) {
            uint32_t ah[2][4], al[2][4];
            int achunk = ks * 2 + asel;
            #pragma unroll
            for (int mt = 0; mt < 2; mt++) {
                int r = mBase + mt * 16 + arow;
                uint32_t off = r * 256 + ((achunk ^ (r & 7)) << 4);
                ldsm_x4(ah[mt], sb + L0_SA_HI + off);
                ldsm_x4(al[mt], sb + L0_SA_LO + off);
            }
            uint32_t bh[2][4], bo[2][4];
            int brow = ks * 16 + brow_in;
            #pragma unroll
            for (int nt2 = 0; nt2 < 2; nt2++) {
                int chunk = ((nBase + nt2 * 16) >> 3) + bsel;
                uint32_t off = brow * 256 + ((chunk ^ (brow & 7)) << 4);
                ldsm_x4_t(bh[nt2], sb + SW_HI + off);
                ldsm_x4_t(bo[nt2], sb + SW_LO + off);
            }
            #pragma unroll
            for (int mt = 0; mt < 2; mt++)
                #pragma unroll
                for (int nt = 0; nt < 4; nt++) {
                    const uint32_t* ph = &bh[nt >> 1][(nt & 1) * 2];
                    const uint32_t* pl = &bo[nt >> 1][(nt & 1) * 2];
                    mma16816(acc[mt][nt], ah[mt], ph);
                    mma16816(acc[mt][nt], al[mt], ph);
                    mma16816(acc[mt][nt], ah[mt], pl);
                }
        }

        #pragma unroll
        for (int nt = 0; nt < 4; nt++) {
            int col = nBase + nt * 8 + c2;
            float2 bi = *(const float2*)(bias + col);
            #pragma unroll
            for (int mt = 0; mt < 2; mt++) {
                int g0 = row0 + mBase + mt * 16 + r0;
                float2 o0 = {acc[mt][nt][0] + bi.x, acc[mt][nt][1] + bi.y};
                *(float2*)(out + (size_t)g0 * DIM + col) = o0;
                float2 o1 = {acc[mt][nt][2] + bi.x, acc[mt][nt][3] + bi.y};
                *(float2*)(out + (size_t)(g0 + 8) * DIM + col) = o1;
            }
        }
        __syncthreads();
    }
}

// ---------------- GATv2 aggregation (ex2 variant) ----------------
__device__ __forceinline__ float leaky_dot(float4 v, float4 x, float4 w) {
    float zx = v.x + x.x, zy = v.y + x.y, zz = v.z + x.z, zw = v.w + x.w;
    zx = fmaxf(zx, NEG_SLOPE * zx);
    zy = fmaxf(zy, NEG_SLOPE * zy);
    zz = fmaxf(zz, NEG_SLOPE * zz);
    zw = fmaxf(zw, NEG_SLOPE * zw);
    return zx * w.x + zy * w.y + zz * w.z + zw * w.w;
}
__device__ __forceinline__ float hred8(float d) {
    d += __shfl_xor_sync(0xffffffffu, d, 1);
    d += __shfl_xor_sync(0xffffffffu, d, 2);
    d += __shfl_xor_sync(0xffffffffu, d, 4);
    return d;
}
__device__ __forceinline__ float ex2(float x) {
    float r;
    asm("ex2.approx.f32 %0, %1;" : "=f"(r) : "f"(x));
    return r;
}

__global__ __launch_bounds__(256) void k_gat(
    const float* __restrict__ xl, const float* __restrict__ xr,
    const float* __restrict__ att, const float* __restrict__ conv_bias,
    const float* __restrict__ bn_gamma, const float* __restrict__ bn_beta,
    const float* __restrict__ bn_mean, const float* __restrict__ bn_var,
    float* __restrict__ hout, int write_bf, int write_f32)
{
    int i = blockIdx.x * 8 + (threadIdx.x >> 5);
    if (i >= NODES) return;
    int lane = threadIdx.x & 31;
    int c = lane * 4;

    float4 w = *(const float4*)(att + c);
    w.x *= LOG2E; w.y *= LOG2E; w.z *= LOG2E; w.w *= LOG2E;
    float4 xr4 = *(const float4*)(xr + (size_t)i * DIM + c);

    float4 xls = *(const float4*)(xl + (size_t)i * DIM + c);
    float m0 = hred8(leaky_dot(xls, xr4, w));
    float denom = 1.0f;
    float4 acc = xls;

    int beg = d_rowptr[i];
    int end = d_rowptr[i + 1];
    int j = beg;
    for (; j + 4 <= end; j += 4) {
        uint32_t s0 = d_srcs[j];
        uint32_t s1 = d_srcs[j + 1];
        uint32_t s2 = d_srcs[j + 2];
        uint32_t s3 = d_srcs[j + 3];
        float4 v0 = *(const float4*)(xl + (size_t)s0 * DIM + c);
        float4 v1 = *(const float4*)(xl + (size_t)s1 * DIM + c);
        float4 v2 = *(const float4*)(xl + (size_t)s2 * DIM + c);
        float4 v3 = *(const float4*)(xl + (size_t)s3 * DIM + c);
        float d0 = hred8(leaky_dot(v0, xr4, w));
        float d1 = hred8(leaky_dot(v1, xr4, w));
        float d2 = hred8(leaky_dot(v2, xr4, w));
        float d3 = hred8(leaky_dot(v3, xr4, w));
        float a0 = ex2(d0 - m0);
        float a1 = ex2(d1 - m0);
        float a2 = ex2(d2 - m0);
        float a3 = ex2(d3 - m0);
        denom += (a0 + a1) + (a2 + a3);
        acc.x += (a0 * v0.x + a1 * v1.x) + (a2 * v2.x + a3 * v3.x);
        acc.y += (a0 * v0.y + a1 * v1.y) + (a2 * v2.y + a3 * v3.y);
        acc.z += (a0 * v0.z + a1 * v1.z) + (a2 * v2.z + a3 * v3.z);
        acc.w += (a0 * v0.w + a1 * v1.w) + (a2 * v2.w + a3 * v3.w);
    }
    for (; j < end; j++) {
        uint32_t s0 = d_srcs[j];
        float4 v0 = *(const float4*)(xl + (size_t)s0 * DIM + c);
        float a0 = ex2(hred8(leaky_dot(v0, xr4, w)) - m0);
        denom += a0;
        acc.x += a0 * v0.x;
        acc.y += a0 * v0.y;
        acc.z += a0 * v0.z;
        acc.w += a0 * v0.w;
    }

    float inv = 1.0f / denom;
    float4 bias = *(const float4*)(conv_bias + c);
    float4 ga = *(const float4*)(bn_gamma + c);
    float4 be = *(const float4*)(bn_beta + c);
    float4 mu = *(const float4*)(bn_mean + c);
    float4 va = *(const float4*)(bn_var + c);
    float4 o;
    o.x = fmaxf((acc.x * inv + bias.x - mu.x) * rsqrtf(va.x + BN_EPS) * ga.x + be.x, 0.f);
    o.y = fmaxf((acc.y * inv + bias.y - mu.y) * rsqrtf(va.y + BN_EPS) * ga.y + be.y, 0.f);
    o.z = fmaxf((acc.z * inv + bias.z - mu.z) * rsqrtf(va.z + BN_EPS) * ga.z + be.z, 0.f);
    o.w = fmaxf((acc.w * inv + bias.w - mu.w) * rsqrtf(va.w + BN_EPS) * ga.w + be.w, 0.f);

    if (write_f32) *(float4*)(hout + (size_t)i * DIM + c) = o;
    if (write_bf) {
        __nv_bfloat16 hx = __float2bfloat16(o.x);
        __nv_bfloat16 hy = __float2bfloat16(o.y);
        __nv_bfloat16 hz = __float2bfloat16(o.z);
        __nv_bfloat16 hw = __float2bfloat16(o.w);
        __nv_bfloat162* ph = (__nv_bfloat162*)(d_hhi + (size_t)i * DIM + c);
        ph[0] = __nv_bfloat162(hx, hy);
        ph[1] = __nv_bfloat162(hz, hw);
        __nv_bfloat162* pl = (__nv_bfloat162*)(d_hlo + (size_t)i * DIM + c);
        pl[0] = __nv_bfloat162(__float2bfloat16(o.x - __bfloat162float(hx)),
                               __float2bfloat16(o.y - __bfloat162float(hy)));
        pl[1] = __nv_bfloat162(__float2bfloat16(o.z - __bfloat162float(hz)),
                               __float2bfloat16(o.w - __bfloat162float(hw)));
    }
}

// ---------------- mean pool (batch sorted) + MLP 128->64->2 ----------------
__global__ void k_pool_mlp(
    const float* __restrict__ h, const int* __restrict__ batch,
    const float* __restrict__ W1, const float* __restrict__ b1,
    const float* __restrict__ W2, const float* __restrict__ b2,
    float* __restrict__ out)
{
    __shared__ float p[DIM];
    __shared__ float hid[64];
    int g = blockIdx.x;
    int t = threadIdx.x;

    int lo = 0, hi = NODES;
    while (lo < hi) { int mid = (lo + hi) >> 1; if (batch[mid] < g) lo = mid + 1; else hi = mid; }
    int beg = lo;
    hi = NODES;
    while (lo < hi) { int mid = (lo + hi) >> 1; if (batch[mid] < g + 1) lo = mid + 1; else hi = mid; }
    int end = lo;

    float sum = 0.f;
    for (int n = beg; n < end; n++) sum += h[(size_t)n * DIM + t];
    float cnt = (float)(end - beg);
    p[t] = sum / fmaxf(cnt, 1.0f);
    __syncthreads();

    if (t < 64) {
        float a = b1[t];
        #pragma unroll 8
        for (int k = 0; k < DIM; k++) a = fmaf(p[k], W1[k * 64 + t], a);
        hid[t] = fmaxf(a, 0.f);
    }
    __syncthreads();

    if (t < 2) {
        float a = b2[t];
        #pragma unroll 8
        for (int k = 0; k < 64; k++) a = fmaf(hid[k], W2[k * 2 + t], a);
        out[g * 2 + t] = a;
    }
}

// ---------------- launch ----------------
extern "C" void kernel_launch(void* const* d_in, const int* in_sizes, int n_in,
                              void* d_out, int out_size)
{
    const float* x     = (const float*)d_in[0];
    const int*   ei    = (const int*)d_in[1];
    const int*   batch = (const int*)d_in[2];
    const float* Wl    = (const float*)d_in[3];
    const float* bl    = (const float*)d_in[4];
    const float* Wr    = (const float*)d_in[5];
    const float* br    = (const float*)d_in[6];
    const float* att   = (const float*)d_in[7];
    const float* cb    = (const float*)d_in[8];
    const float* bng   = (const float*)d_in[9];
    const float* bnb   = (const float*)d_in[10];
    const float* bnm   = (const float*)d_in[11];
    const float* bnv   = (const float*)d_in[12];
    const float* W1    = (const float*)d_in[13];
    const float* b1    = (const float*)d_in[14];
    const float* W2    = (const float*)d_in[15];
    const float* b2    = (const float*)d_in[16];
    float* out = (float*)d_out;

    float *h0, *xl, *xr;
    __nv_bfloat16 *hhi, *hlo, *whi, *wlo;
    cudaGetSymbolAddress((void**)&h0, d_h0);
    cudaGetSymbolAddress((void**)&xl, d_xl);
    cudaGetSymbolAddress((void**)&xr, d_xr);
    cudaGetSymbolAddress((void**)&hhi, d_hhi);
    cudaGetSymbolAddress((void**)&hlo, d_hlo);
    cudaGetSymbolAddress((void**)&whi, d_whi);
    cudaGetSymbolAddress((void**)&wlo, d_wlo);

    static int init_done = 0;
    static cudaStream_t s2;
    static cudaEvent_t evA, evB;
    if (!init_done) {
        cudaFuncSetAttribute(k_gemm_tc, cudaFuncAttributeMaxDynamicSharedMemorySize, GSMEM);
        cudaFuncSetAttribute(k_gemm_l0, cudaFuncAttributeMaxDynamicSharedMemorySize, GSMEM_L0);
        cudaStreamCreateWithFlags(&s2, cudaStreamNonBlocking);
        cudaEventCreateWithFlags(&evA, cudaEventDisableTiming);
        cudaEventCreateWithFlags(&evB, cudaEventDisableTiming);
        init_done = 1;
    }

    dim3 ggrid(74, 2);

    // fork s2 at t=0: full CSR chain runs concurrently with W-convert + GEMM L0
    cudaEventRecord(evA, 0);
    cudaStreamWaitEvent(s2, evA, 0);
    k_zero<<<(NODES + 255) / 256, 256, 0, s2>>>();                    // #0 (s2)
    k_hist<<<(EDGES + 255) / 256, 256, 0, s2>>>(ei);                  // #1 (s2)
    k_conv_w<<<6, 256>>>(Wl, Wr);                                     // #2 (main)
    k_gemm_l0<<<ggrid, 256, GSMEM_L0>>>(x, whi, wlo, bl, br);         // #3 (main) <-- profiled
    k_scan<<<1, 1024, 0, s2>>>();                                     // #4 (s2)
    k_scatter<<<(EDGES + 255) / 256, 256, 0, s2>>>(ei);               // #5 (s2)
    cudaEventRecord(evB, s2);
    cudaStreamWaitEvent(0, evB, 0);

    for (int l = 0; l < 3; l++) {
        if (l > 0) {
            k_gemm_tc<<<ggrid, 256, GSMEM>>>(
                hhi, hlo,
                whi + (size_t)l * 2 * DIM * DIM, wlo + (size_t)l * 2 * DIM * DIM,
                bl + l * DIM, br + l * DIM);
        }
        k_gat<<<NODES / 8, 256>>>(xl, xr,
                                  att + l * DIM, cb + l * DIM,
                                  bng + l * DIM, bnb + l * DIM,
                                  bnm + l * DIM, bnv + l * DIM,
                                  h0, (l < 2) ? 1 : 0, (l == 2) ? 1 : 0);
    }

    k_pool_mlp<<<GRAPHS, 128>>>(h0, batch, W1, b1, W2, b2, out);
}